// round 1
// baseline (speedup 1.0000x reference)
#include <cuda_runtime.h>
#include <math.h>

// ---------------------------------------------------------------------------
// Problem constants
// ---------------------------------------------------------------------------
constexpr int B_  = 8192;
constexpr int H_  = 768;
constexpr int S_  = 12;
constexpr int FF_ = 2048;
constexpr int MR_ = B_ * S_;   // 98304 flattened rows

// ---------------------------------------------------------------------------
// Scratch (static device globals — allocation-free per harness rules)
// ---------------------------------------------------------------------------
__device__ float g_gseq[(size_t)MR_ * H_];
__device__ float g_Q   [(size_t)MR_ * H_];
__device__ float g_K   [(size_t)MR_ * H_];
__device__ float g_V   [(size_t)MR_ * H_];
__device__ float g_P   [(size_t)MR_ * H_];
__device__ float g_Y   [(size_t)MR_ * H_];
__device__ float g_X1  [(size_t)MR_ * H_];
__device__ float g_X2  [(size_t)MR_ * H_];
__device__ float g_FF  [(size_t)MR_ * FF_];
__device__ float g_lpool[(size_t)B_ * H_];
__device__ float g_xd  [(size_t)B_ * H_];
__device__ float g_xl  [(size_t)B_ * H_];
__device__ int   g_len [B_];

// ---------------------------------------------------------------------------
// Helpers
// ---------------------------------------------------------------------------
__device__ __forceinline__ unsigned f2tf(float x) {
    unsigned r;
    asm("cvt.rna.tf32.f32 %0, %1;" : "=r"(r) : "f"(x));
    return r;
}

__device__ __forceinline__ void cpasync16(void* s, const void* g) {
    unsigned sa = (unsigned)__cvta_generic_to_shared(s);
    asm volatile("cp.async.cg.shared.global [%0], [%1], 16;\n" :: "r"(sa), "l"(g));
}

__device__ __forceinline__ float warp_red(float v) {
#pragma unroll
    for (int o = 16; o > 0; o >>= 1) v += __shfl_xor_sync(0xffffffffu, v, o);
    return v;
}

// ---------------------------------------------------------------------------
// 1. Gather: build gseq (oldest-first history, zero pad, z_k at row 11),
//    lpool (4-slot mean with faithful zero-row / conditional-z_k quirk), L.
// ---------------------------------------------------------------------------
__global__ void gather_kernel(const float* __restrict__ z_k,
                              const float* __restrict__ buf,
                              const int*   __restrict__ mask,
                              const int*   __restrict__ bidx) {
    const int b = blockIdx.x;
    const int tid = threadIdx.x; // 128
    __shared__ int ord[12];
    __shared__ int s_nv;
    if (tid == 0) {
        int idx = bidx[b];
        int cnt = 0;
        // ages: slot s has age (idx - s) mod 12; oldest first = a from 11 down to 0
        for (int a = 11; a >= 0; a--) {
            int s = (idx - a + 24) % 12;
            if (mask[b * 12 + s]) ord[cnt++] = s;
        }
        s_nv = cnt;
        int hlen = cnt < 11 ? cnt : 11;
        g_len[b] = hlen + 1;
    }
    __syncthreads();
    const int nv = s_nv;
    const int hlen = nv < 11 ? nv : 11;
    const float* zb = z_k + (size_t)b * H_;

    for (int t = 0; t < 12; t++) {
        float* dst = g_gseq + ((size_t)(b * 12 + t)) * H_;
        if (t < hlen) {
            const float* src = buf + ((size_t)(b * 12 + ord[t])) * H_;
            for (int i = tid; i < H_; i += 128) dst[i] = src[i];
        } else if (t == 11) {
            for (int i = tid; i < H_; i += 128) dst[i] = zb[i];
        } else {
            for (int i = tid; i < H_; i += 128) dst[i] = 0.f;
        }
    }

    const int c4 = nv < 4 ? nv : 4;
    const float inv = 1.f / (float)(c4 + 1);
    for (int i = tid; i < H_; i += 128) {
        float s = 0.f;
        for (int t = 0; t < c4; t++)
            s += buf[((size_t)(b * 12 + ord[t])) * H_ + i];
        if (c4 == 4) s += zb[i];
        g_lpool[(size_t)b * H_ + i] = s * inv;
    }
}

// ---------------------------------------------------------------------------
// 2. Generic tf32 GEMM: C[M,N] = epi(A[M,K] @ W[K,N] + bias [+resid])
//    BM=128 BN=128 BK=16, 256 threads, 2-stage cp.async pipeline,
//    mma.sync.m16n8k8 tf32. All dims divisible by tiles (asserted by usage).
//    epi: 0 = none, 1 = +resid, 2 = relu, 3 = tanh
// ---------------------------------------------------------------------------
#define BM 128
#define BN 128
#define BK 16

__global__ void __launch_bounds__(256) gemm_tf32(
    const float* __restrict__ A, const float* __restrict__ W,
    const float* __restrict__ bias, const float* __restrict__ resid,
    float* __restrict__ C, int M, int N, int K, int epi)
{
    __shared__ float As[2][BM][20];   // 16 cols + pad (stride 20: 16B aligned, conflict-free)
    __shared__ float Bs[2][BK][136];  // 128 cols + pad (stride 136: conflict-free b-frags)

    const int tid  = threadIdx.x;
    const int bn   = blockIdx.x, bm = blockIdx.y;
    const int warp = tid >> 5, lane = tid & 31;
    const int wm   = (warp & 1) * 64;    // 2 warps along M
    const int wn   = (warp >> 1) * 32;   // 4 warps along N
    const int g    = lane >> 2, tg = lane & 3;

    const float* Ab = A + (size_t)bm * BM * K;
    const float* Wb = W + (size_t)bn * BN;

    float acc[4][4][4];
#pragma unroll
    for (int mi = 0; mi < 4; mi++)
#pragma unroll
        for (int ni = 0; ni < 4; ni++)
#pragma unroll
            for (int r = 0; r < 4; r++) acc[mi][ni][r] = 0.f;

    auto load_tiles = [&](int kt, int bufi) {
        const int k0 = kt * BK;
#pragma unroll
        for (int i = tid; i < 512; i += 256) {       // A: 128x16 = 512 float4
            int r = i >> 2, c = (i & 3) * 4;
            cpasync16(&As[bufi][r][c], Ab + (size_t)r * K + k0 + c);
        }
#pragma unroll
        for (int i = tid; i < 512; i += 256) {       // B: 16x128 = 512 float4
            int r = i >> 5, c = (i & 31) * 4;
            cpasync16(&Bs[bufi][r][c], Wb + (size_t)(k0 + r) * N + c);
        }
    };

    const int KT = K / BK;
    load_tiles(0, 0);
    asm volatile("cp.async.commit_group;\n");

    for (int kt = 0; kt < KT; kt++) {
        const int bufi = kt & 1;
        asm volatile("cp.async.wait_group 0;\n");
        __syncthreads();
        if (kt + 1 < KT) {
            load_tiles(kt + 1, bufi ^ 1);
            asm volatile("cp.async.commit_group;\n");
        }
#pragma unroll
        for (int ks = 0; ks < BK; ks += 8) {
            unsigned a[4][4], bfr[4][2];
#pragma unroll
            for (int mi = 0; mi < 4; mi++) {
                int r = wm + mi * 16 + g;
                a[mi][0] = f2tf(As[bufi][r    ][ks + tg    ]);
                a[mi][1] = f2tf(As[bufi][r + 8][ks + tg    ]);
                a[mi][2] = f2tf(As[bufi][r    ][ks + tg + 4]);
                a[mi][3] = f2tf(As[bufi][r + 8][ks + tg + 4]);
            }
#pragma unroll
            for (int ni = 0; ni < 4; ni++) {
                int c = wn + ni * 8 + g;
                bfr[ni][0] = f2tf(Bs[bufi][ks + tg    ][c]);
                bfr[ni][1] = f2tf(Bs[bufi][ks + tg + 4][c]);
            }
#pragma unroll
            for (int mi = 0; mi < 4; mi++)
#pragma unroll
                for (int ni = 0; ni < 4; ni++)
                    asm volatile(
                        "mma.sync.aligned.m16n8k8.row.col.f32.tf32.tf32.f32 "
                        "{%0,%1,%2,%3}, {%4,%5,%6,%7}, {%8,%9}, {%0,%1,%2,%3};\n"
                        : "+f"(acc[mi][ni][0]), "+f"(acc[mi][ni][1]),
                          "+f"(acc[mi][ni][2]), "+f"(acc[mi][ni][3])
                        : "r"(a[mi][0]), "r"(a[mi][1]), "r"(a[mi][2]), "r"(a[mi][3]),
                          "r"(bfr[ni][0]), "r"(bfr[ni][1]));
        }
    }

    // Epilogue
    const int rowBase = bm * BM + wm;
    const int colBase = bn * BN + wn;
#pragma unroll
    for (int mi = 0; mi < 4; mi++) {
#pragma unroll
        for (int ni = 0; ni < 4; ni++) {
            int c0 = colBase + ni * 8 + tg * 2;
            float b0 = bias[c0], b1 = bias[c0 + 1];
#pragma unroll
            for (int hh = 0; hh < 2; hh++) {
                int row = rowBase + mi * 16 + g + hh * 8;
                float v0 = acc[mi][ni][hh * 2]     + b0;
                float v1 = acc[mi][ni][hh * 2 + 1] + b1;
                size_t off = (size_t)row * N + c0;
                if (epi == 1)      { v0 += resid[off]; v1 += resid[off + 1]; }
                else if (epi == 2) { v0 = fmaxf(v0, 0.f); v1 = fmaxf(v1, 0.f); }
                else if (epi == 3) { v0 = tanhf(v0); v1 = tanhf(v1); }
                C[off]     = v0;
                C[off + 1] = v1;
            }
        }
    }
}

// ---------------------------------------------------------------------------
// 3. Attention: one CTA per (batch, head). S=12, HD=96. Key-masked softmax.
// ---------------------------------------------------------------------------
__global__ void attn_kernel() {
    const int b = blockIdx.x, h = blockIdx.y;
    __shared__ float q[12][97], k[12][97], v[12][97];
    __shared__ float sc[12][12];
    const int tid = threadIdx.x; // 128
    const size_t base = (size_t)b * 12 * H_ + h * 96;

    for (int i = tid; i < 12 * 96; i += 128) {
        int t = i / 96, d = i % 96;
        size_t o = base + (size_t)t * H_ + d;
        q[t][d] = g_Q[o];
        k[t][d] = g_K[o];
        v[t][d] = g_V[o];
    }
    __syncthreads();
    const int L = g_len[b];

    for (int p = tid; p < 144; p += 128) {
        int qi = p / 12, ki = p % 12;
        float s = 0.f;
#pragma unroll
        for (int d = 0; d < 96; d++) s += q[qi][d] * k[ki][d];
        sc[qi][ki] = (ki < L) ? s * 0.10206207261596577f : -1e9f;
    }
    __syncthreads();

    if (tid < 12) {
        float m = -3.0e38f;
        for (int j = 0; j < 12; j++) m = fmaxf(m, sc[tid][j]);
        float sum = 0.f;
        for (int j = 0; j < 12; j++) { float e = expf(sc[tid][j] - m); sc[tid][j] = e; sum += e; }
        float r = 1.f / sum;
        for (int j = 0; j < 12; j++) sc[tid][j] *= r;
    }
    __syncthreads();

    for (int i = tid; i < 12 * 96; i += 128) {
        int qi = i / 96, d = i % 96;
        float o = 0.f;
#pragma unroll
        for (int j = 0; j < 12; j++) o += sc[qi][j] * v[j][d];
        g_P[base + (size_t)qi * H_ + d] = o;
    }
}

// ---------------------------------------------------------------------------
// 4. Row LayerNorm over H=768 (one CTA per row, 256 threads)
// ---------------------------------------------------------------------------
__global__ void ln_kernel(const float* __restrict__ X,
                          const float* __restrict__ gam,
                          const float* __restrict__ bet,
                          float* __restrict__ O) {
    const int row = blockIdx.x;
    const int tid = threadIdx.x; // 256
    const float* x = X + (size_t)row * H_;
    float vals[3];
    float s = 0.f, s2 = 0.f;
#pragma unroll
    for (int i = 0; i < 3; i++) {
        float t = x[tid + i * 256];
        vals[i] = t; s += t; s2 += t * t;
    }
    __shared__ float red[2][8];
    s  = warp_red(s);
    s2 = warp_red(s2);
    if ((tid & 31) == 0) { red[0][tid >> 5] = s; red[1][tid >> 5] = s2; }
    __syncthreads();
    float ts = 0.f, ts2 = 0.f;
#pragma unroll
    for (int w = 0; w < 8; w++) { ts += red[0][w]; ts2 += red[1][w]; }
    const float mu  = ts * (1.f / 768.f);
    const float var = ts2 * (1.f / 768.f) - mu * mu;
    const float inv = rsqrtf(var + 1e-5f);
    float* o = O + (size_t)row * H_;
#pragma unroll
    for (int i = 0; i < 3; i++) {
        int c = tid + i * 256;
        o[c] = (vals[i] - mu) * inv * gam[c] + bet[c];
    }
}

// ---------------------------------------------------------------------------
// 5. Final: x_g pool, 3-way gate softmax, output mix. One CTA per batch elem.
// ---------------------------------------------------------------------------
__global__ void final_kernel(const float* __restrict__ Wg,
                             const float* __restrict__ bg,
                             float* __restrict__ out) {
    const int b = blockIdx.x, tid = threadIdx.x; // 256
    const int L = g_len[b];
    const float invL = 1.f / (float)L;
    float xd[3], xl[3], xg[3];
    float p0 = 0.f, p1 = 0.f, p2 = 0.f;
#pragma unroll
    for (int i = 0; i < 3; i++) {
        int c = tid + i * 256;
        size_t bo = (size_t)b * H_ + c;
        xd[i] = g_xd[bo];
        xl[i] = g_xl[bo];
        float s = 0.f;
        for (int t = 0; t < L; t++)
            s += g_X2[((size_t)(b * 12 + t)) * H_ + c];
        xg[i] = s * invL;
        p0 += xd[i] * Wg[c * 3 + 0] + xl[i] * Wg[(768 + c) * 3 + 0] + xg[i] * Wg[(1536 + c) * 3 + 0];
        p1 += xd[i] * Wg[c * 3 + 1] + xl[i] * Wg[(768 + c) * 3 + 1] + xg[i] * Wg[(1536 + c) * 3 + 1];
        p2 += xd[i] * Wg[c * 3 + 2] + xl[i] * Wg[(768 + c) * 3 + 2] + xg[i] * Wg[(1536 + c) * 3 + 2];
    }
    p0 = warp_red(p0); p1 = warp_red(p1); p2 = warp_red(p2);
    __shared__ float red[8][3];
    if ((tid & 31) == 0) { red[tid >> 5][0] = p0; red[tid >> 5][1] = p1; red[tid >> 5][2] = p2; }
    __syncthreads();
    float l0 = bg[0], l1 = bg[1], l2 = bg[2];
#pragma unroll
    for (int w = 0; w < 8; w++) { l0 += red[w][0]; l1 += red[w][1]; l2 += red[w][2]; }
    float m  = fmaxf(l0, fmaxf(l1, l2));
    float e0 = expf(l0 - m), e1 = expf(l1 - m), e2 = expf(l2 - m);
    float rs = 1.f / (e0 + e1 + e2);
    float g0 = e0 * rs, g1 = e1 * rs, g2 = e2 * rs;
#pragma unroll
    for (int i = 0; i < 3; i++) {
        int c = tid + i * 256;
        out[(size_t)b * H_ + c] = g0 * xd[i] + g1 * xl[i] + g2 * xg[i];
    }
}

// ---------------------------------------------------------------------------
// Launch
// ---------------------------------------------------------------------------
extern "C" void kernel_launch(void* const* d_in, const int* in_sizes, int n_in,
                              void* d_out, int out_size) {
    const float* z_k  = (const float*)d_in[0];
    const float* ctx  = (const float*)d_in[1];
    const int*   mask = (const int*)  d_in[2];
    const int*   bidx = (const int*)  d_in[3];
    const float* Wq = (const float*)d_in[4];  const float* bq = (const float*)d_in[5];
    const float* Wk = (const float*)d_in[6];  const float* bk = (const float*)d_in[7];
    const float* Wv = (const float*)d_in[8];  const float* bv = (const float*)d_in[9];
    const float* Wo = (const float*)d_in[10]; const float* bo = (const float*)d_in[11];
    const float* ln1g = (const float*)d_in[12]; const float* ln1b = (const float*)d_in[13];
    const float* W1 = (const float*)d_in[14]; const float* b1 = (const float*)d_in[15];
    const float* W2 = (const float*)d_in[16]; const float* b2 = (const float*)d_in[17];
    const float* ln2g = (const float*)d_in[18]; const float* ln2b = (const float*)d_in[19];
    const float* Wd = (const float*)d_in[20]; const float* bd = (const float*)d_in[21];
    const float* Wl = (const float*)d_in[22]; const float* bl = (const float*)d_in[23];
    const float* Wg = (const float*)d_in[24]; const float* bg = (const float*)d_in[25];
    float* out = (float*)d_out;

    void *pgseq, *pQ, *pK, *pV, *pP, *pY, *pX1, *pX2, *pFF, *plp, *pxd, *pxl;
    cudaGetSymbolAddress(&pgseq, g_gseq);
    cudaGetSymbolAddress(&pQ,  g_Q);
    cudaGetSymbolAddress(&pK,  g_K);
    cudaGetSymbolAddress(&pV,  g_V);
    cudaGetSymbolAddress(&pP,  g_P);
    cudaGetSymbolAddress(&pY,  g_Y);
    cudaGetSymbolAddress(&pX1, g_X1);
    cudaGetSymbolAddress(&pX2, g_X2);
    cudaGetSymbolAddress(&pFF, g_FF);
    cudaGetSymbolAddress(&plp, g_lpool);
    cudaGetSymbolAddress(&pxd, g_xd);
    cudaGetSymbolAddress(&pxl, g_xl);

    const float* fgseq = (const float*)pgseq;
    float* fQ  = (float*)pQ;   float* fK  = (float*)pK;   float* fV = (float*)pV;
    float* fP  = (float*)pP;   float* fY  = (float*)pY;
    float* fX1 = (float*)pX1;  float* fX2 = (float*)pX2;  float* fFF = (float*)pFF;
    float* flp = (float*)plp;  float* fxd = (float*)pxd;  float* fxl = (float*)pxl;

    gather_kernel<<<B_, 128>>>(z_k, ctx, mask, bidx);

    dim3 thr(256);
    // QKV projections
    gemm_tf32<<<dim3(H_ / BN, MR_ / BM), thr>>>(fgseq, Wq, bq, nullptr, fQ, MR_, H_, H_, 0);
    gemm_tf32<<<dim3(H_ / BN, MR_ / BM), thr>>>(fgseq, Wk, bk, nullptr, fK, MR_, H_, H_, 0);
    gemm_tf32<<<dim3(H_ / BN, MR_ / BM), thr>>>(fgseq, Wv, bv, nullptr, fV, MR_, H_, H_, 0);
    // Attention
    attn_kernel<<<dim3(B_, 8), 128>>>();
    // Output projection + residual (gseq), LN1
    gemm_tf32<<<dim3(H_ / BN, MR_ / BM), thr>>>(fP, Wo, bo, fgseq, fY, MR_, H_, H_, 1);
    ln_kernel<<<MR_, 256>>>(fY, ln1g, ln1b, fX1);
    // FFN
    gemm_tf32<<<dim3(FF_ / BN, MR_ / BM), thr>>>(fX1, W1, b1, nullptr, fFF, MR_, FF_, H_, 2);
    gemm_tf32<<<dim3(H_ / BN, MR_ / BM), thr>>>(fFF, W2, b2, fX1, fY, MR_, H_, FF_, 1);
    ln_kernel<<<MR_, 256>>>(fY, ln2g, ln2b, fX2);
    // Direct & local paths
    gemm_tf32<<<dim3(H_ / BN, B_ / BM), thr>>>(z_k, Wd, bd, nullptr, fxd, B_, H_, H_, 3);
    gemm_tf32<<<dim3(H_ / BN, B_ / BM), thr>>>(flp, Wl, bl, nullptr, fxl, B_, H_, H_, 3);
    // Gate + output
    final_kernel<<<B_, 256>>>(Wg, bg, out);
}

// round 3
// speedup vs baseline: 2.1115x; 2.1115x over previous
#include <cuda_runtime.h>
#include <cuda_fp16.h>
#include <math.h>
#include <stdint.h>

// ---------------------------------------------------------------------------
// Problem constants
// ---------------------------------------------------------------------------
constexpr int B_   = 8192;
constexpr int H_   = 768;
constexpr int H3_  = 2304;
constexpr int FF_  = 2048;
constexpr int MR_  = B_ * 12;   // 98304 flattened rows

// ---------------------------------------------------------------------------
// Scratch (static device globals)
// ---------------------------------------------------------------------------
__device__ __align__(256) float  g_gseqf[(size_t)MR_ * H_];
__device__ __align__(256) __half g_gseqh[(size_t)MR_ * H_];
__device__ __align__(256) float  g_QKV [(size_t)MR_ * H3_];
__device__ __align__(256) __half g_Ph  [(size_t)MR_ * H_];
__device__ __align__(256) float  g_Y   [(size_t)MR_ * H_];
__device__ __align__(256) float  g_X1f [(size_t)MR_ * H_];
__device__ __align__(256) __half g_X1h [(size_t)MR_ * H_];
__device__ __align__(256) __half g_FFh [(size_t)MR_ * FF_];
__device__ __align__(256) float  g_X2  [(size_t)MR_ * H_];
__device__ __align__(256) __half g_lph [(size_t)B_ * H_];
__device__ __align__(256) __half g_zh  [(size_t)B_ * H_];
__device__ __align__(256) float  g_xd  [(size_t)B_ * H_];
__device__ __align__(256) float  g_xl  [(size_t)B_ * H_];
__device__ int   g_len[B_];
__device__ float g_bqkv[H3_];

// Half weight arena ([K][N] row-major, NOT transposed)
constexpr size_t OFF_QKV = 0;                                  // [768][2304]
constexpr size_t OFF_WO  = OFF_QKV + (size_t)H_ * H3_;         // [768][768]
constexpr size_t OFF_W1  = OFF_WO  + (size_t)H_ * H_;          // [768][2048]
constexpr size_t OFF_W2  = OFF_W1  + (size_t)H_ * FF_;         // [2048][768]
constexpr size_t OFF_WD  = OFF_W2  + (size_t)FF_ * H_;         // [768][768]
constexpr size_t OFF_WL  = OFF_WD  + (size_t)H_ * H_;          // [768][768]
__device__ __align__(256) __half g_Wh[OFF_WL + (size_t)H_ * H_];

// ---------------------------------------------------------------------------
// Helpers
// ---------------------------------------------------------------------------
__device__ __forceinline__ void cpasync16(uint32_t saddr, const void* g) {
    asm volatile("cp.async.cg.shared.global [%0], [%1], 16;\n" :: "r"(saddr), "l"(g));
}
__device__ __forceinline__ float warp_red(float v) {
#pragma unroll
    for (int o = 16; o > 0; o >>= 1) v += __shfl_xor_sync(0xffffffffu, v, o);
    return v;
}
__device__ __forceinline__ void ldsm4(uint32_t* r, uint32_t addr) {
    asm volatile("ldmatrix.sync.aligned.m8n8.x4.shared.b16 {%0,%1,%2,%3}, [%4];\n"
                 : "=r"(r[0]), "=r"(r[1]), "=r"(r[2]), "=r"(r[3]) : "r"(addr));
}
__device__ __forceinline__ void ldsm4t(uint32_t* r, uint32_t addr) {
    asm volatile("ldmatrix.sync.aligned.m8n8.x4.trans.shared.b16 {%0,%1,%2,%3}, [%4];\n"
                 : "=r"(r[0]), "=r"(r[1]), "=r"(r[2]), "=r"(r[3]) : "r"(addr));
}
__device__ __forceinline__ void mma16816(float* c, const uint32_t* a, uint32_t b0, uint32_t b1) {
    asm volatile(
        "mma.sync.aligned.m16n8k16.row.col.f32.f16.f16.f32 "
        "{%0,%1,%2,%3}, {%4,%5,%6,%7}, {%8,%9}, {%0,%1,%2,%3};\n"
        : "+f"(c[0]), "+f"(c[1]), "+f"(c[2]), "+f"(c[3])
        : "r"(a[0]), "r"(a[1]), "r"(a[2]), "r"(a[3]), "r"(b0), "r"(b1));
}

// ---------------------------------------------------------------------------
// Weight prep
// ---------------------------------------------------------------------------
__global__ void pack_qkv(const float* __restrict__ Wq, const float* __restrict__ Wk,
                         const float* __restrict__ Wv, __half* __restrict__ dst) {
    int i = blockIdx.x * 256 + threadIdx.x;
    if (i >= H_ * H_) return;
    int r = i / H_, c = i % H_;
    size_t o = (size_t)r * H3_ + c;
    dst[o]          = __float2half_rn(Wq[i]);
    dst[o + H_]     = __float2half_rn(Wk[i]);
    dst[o + 2 * H_] = __float2half_rn(Wv[i]);
}
__global__ void convh(const float* __restrict__ src, __half* __restrict__ dst, int n) {
    int i = blockIdx.x * 256 + threadIdx.x;
    if (i < n) dst[i] = __float2half_rn(src[i]);
}
__global__ void pack_bias(const float* __restrict__ bq, const float* __restrict__ bk,
                          const float* __restrict__ bv, float* __restrict__ dst) {
    int i = threadIdx.x + blockIdx.x * 256;
    if (i < H_) { dst[i] = bq[i]; dst[i + H_] = bk[i]; dst[i + 2 * H_] = bv[i]; }
}

// ---------------------------------------------------------------------------
// Gather: gseq (fp32 + half), lpool (half), z (half), lengths
// ---------------------------------------------------------------------------
__global__ void gather_kernel(const float* __restrict__ z_k,
                              const float* __restrict__ buf,
                              const int*   __restrict__ mask,
                              const int*   __restrict__ bidx) {
    const int b = blockIdx.x;
    const int tid = threadIdx.x; // 128
    __shared__ int ord[12];
    __shared__ int s_nv;
    if (tid == 0) {
        int idx = bidx[b];
        int cnt = 0;
        for (int a = 11; a >= 0; a--) {
            int s = (idx - a + 24) % 12;
            if (mask[b * 12 + s]) ord[cnt++] = s;
        }
        s_nv = cnt;
        int hlen = cnt < 11 ? cnt : 11;
        g_len[b] = hlen + 1;
    }
    __syncthreads();
    const int nv = s_nv;
    const int hlen = nv < 11 ? nv : 11;
    const float* zb = z_k + (size_t)b * H_;

    for (int t = 0; t < 12; t++) {
        size_t doff = ((size_t)(b * 12 + t)) * H_;
        if (t < hlen) {
            const float* src = buf + ((size_t)(b * 12 + ord[t])) * H_;
            for (int i = tid; i < H_; i += 128) {
                float v = src[i];
                g_gseqf[doff + i] = v;
                g_gseqh[doff + i] = __float2half_rn(v);
            }
        } else if (t == 11) {
            for (int i = tid; i < H_; i += 128) {
                float v = zb[i];
                g_gseqf[doff + i] = v;
                g_gseqh[doff + i] = __float2half_rn(v);
            }
        } else {
            for (int i = tid; i < H_; i += 128) {
                g_gseqf[doff + i] = 0.f;
                g_gseqh[doff + i] = __half(0.f);
            }
        }
    }

    const int c4 = nv < 4 ? nv : 4;
    const float inv = 1.f / (float)(c4 + 1);
    for (int i = tid; i < H_; i += 128) {
        float s = 0.f;
        for (int t = 0; t < c4; t++)
            s += buf[((size_t)(b * 12 + ord[t])) * H_ + i];
        if (c4 == 4) s += zb[i];
        g_lph[(size_t)b * H_ + i] = __float2half_rn(s * inv);
        g_zh [(size_t)b * H_ + i] = __float2half_rn(zb[i]);
    }
}

// ---------------------------------------------------------------------------
// fp16 tensor-core GEMM: C[M,N] = epi(A[M,K] @ W[K,N] + bias [+resid])
//   CTA tile 128x128, BK = 32 halves, 4-stage cp.async, ldmatrix + mma16816.
//   epi: 0 fp32 out, 1 fp32 out + resid, 2 relu -> half out, 3 tanh fp32 out
// ---------------------------------------------------------------------------
#define NSTG 4
constexpr int A_STRIDE_B = 80;    // bytes per A smem row (32 halves + pad)
constexpr int B_STRIDE_B = 272;   // bytes per B smem row (128 halves + pad)
constexpr int A_BYTES = 128 * A_STRIDE_B;  // 10240
constexpr int B_BYTES = 32 * B_STRIDE_B;   // 8704
constexpr int STAGE   = A_BYTES + B_BYTES; // 18944

__global__ void __launch_bounds__(256, 2)
gemm_f16(const __half* __restrict__ A, const __half* __restrict__ W,
         const float* __restrict__ bias, const float* __restrict__ resid,
         void* __restrict__ Cout, int M, int N, int K, int epi)
{
    extern __shared__ __align__(16) char smc[];
    const int tid = threadIdx.x, wid = tid >> 5, lane = tid & 31;
    const int bn = blockIdx.x, bm = blockIdx.y;
    const int wm = (wid & 1) * 64;    // 2 warps along M
    const int wn = (wid >> 1) * 32;   // 4 warps along N

    const uint32_t sbase = (uint32_t)__cvta_generic_to_shared(smc);
    const __half* Ab = A + (size_t)(bm * 128) * K;

    float acc[4][4][4];
#pragma unroll
    for (int mi = 0; mi < 4; mi++)
#pragma unroll
        for (int ni = 0; ni < 4; ni++)
#pragma unroll
            for (int r = 0; r < 4; r++) acc[mi][ni][r] = 0.f;

    auto load_stage = [&](int s, int kt) {
        uint32_t as = sbase + s * STAGE;
        uint32_t bs = as + A_BYTES;
        const __half* Ak = Ab + kt * 32;
        const __half* Wk = W + (size_t)(kt * 32) * N + bn * 128;
#pragma unroll
        for (int i = 0; i < 2; i++) {              // A: 512 chunks of 16B
            int idx = tid + (i << 8);
            int r = idx >> 2, c = idx & 3;
            cpasync16(as + r * A_STRIDE_B + c * 16, Ak + (size_t)r * K + c * 8);
        }
#pragma unroll
        for (int i = 0; i < 2; i++) {              // B: 512 chunks of 16B
            int idx = tid + (i << 8);
            int r = idx >> 4, c = idx & 15;
            cpasync16(bs + r * B_STRIDE_B + c * 16, Wk + (size_t)r * N + c * 8);
        }
        asm volatile("cp.async.commit_group;\n" ::: "memory");
    };

    const int NIT = K >> 5;
#pragma unroll
    for (int s = 0; s < NSTG - 1; s++) load_stage(s, s);

    // Loop-invariant lane offsets
    const int l15 = lane & 15;
    const int l16 = (lane >> 4) << 3;   // 0 or 8

    for (int it = 0; it < NIT; it++) {
        asm volatile("cp.async.wait_group %0;\n" :: "n"(NSTG - 2) : "memory");
        __syncthreads();
        if (it + NSTG - 1 < NIT) load_stage((it + NSTG - 1) & (NSTG - 1), it + NSTG - 1);
        else asm volatile("cp.async.commit_group;\n" ::: "memory");

        const int s = it & (NSTG - 1);
        const uint32_t as = sbase + s * STAGE;
        const uint32_t bs = as + A_BYTES;
#pragma unroll
        for (int kh = 0; kh < 2; kh++) {
            const int kc = kh * 16;   // k offset in halves
            uint32_t a[4][4], b[2][4];
#pragma unroll
            for (int mi = 0; mi < 4; mi++) {
                uint32_t addr = as + (wm + mi * 16 + l15) * A_STRIDE_B + (kc + l16) * 2;
                ldsm4(a[mi], addr);
            }
#pragma unroll
            for (int np = 0; np < 2; np++) {
                uint32_t addr = bs + (kc + l15) * B_STRIDE_B + (wn + np * 16 + l16) * 2;
                ldsm4t(b[np], addr);
            }
#pragma unroll
            for (int mi = 0; mi < 4; mi++)
#pragma unroll
                for (int ni = 0; ni < 4; ni++)
                    mma16816(acc[mi][ni], a[mi],
                             b[ni >> 1][(ni & 1) * 2], b[ni >> 1][(ni & 1) * 2 + 1]);
        }
    }

    // Epilogue
    const int g = lane >> 2, tg = lane & 3;
    const int row0 = bm * 128 + wm;
    const int col0 = bn * 128 + wn;
#pragma unroll
    for (int mi = 0; mi < 4; mi++) {
#pragma unroll
        for (int ni = 0; ni < 4; ni++) {
            const int c = col0 + ni * 8 + tg * 2;
            float2 bv = *(const float2*)(bias + c);
#pragma unroll
            for (int hh = 0; hh < 2; hh++) {
                const int r = row0 + mi * 16 + g + hh * 8;
                float v0 = acc[mi][ni][hh * 2]     + bv.x;
                float v1 = acc[mi][ni][hh * 2 + 1] + bv.y;
                const size_t off = (size_t)r * N + c;
                if (epi == 1) {
                    float2 rv = *(const float2*)(resid + off);
                    v0 += rv.x; v1 += rv.y;
                    *(float2*)((float*)Cout + off) = make_float2(v0, v1);
                } else if (epi == 2) {
                    v0 = fmaxf(v0, 0.f); v1 = fmaxf(v1, 0.f);
                    *(__half2*)((__half*)Cout + off) = __floats2half2_rn(v0, v1);
                } else if (epi == 3) {
                    *(float2*)((float*)Cout + off) = make_float2(tanhf(v0), tanhf(v1));
                } else {
                    *(float2*)((float*)Cout + off) = make_float2(v0, v1);
                }
            }
        }
    }
}

// ---------------------------------------------------------------------------
// Attention: one CTA per (batch, head). Reads combined QKV (fp32, N=2304).
// ---------------------------------------------------------------------------
__global__ void attn_kernel() {
    const int b = blockIdx.x, h = blockIdx.y;
    __shared__ float q[12][97], k[12][97], v[12][97];
    __shared__ float sc[12][12];
    const int tid = threadIdx.x; // 128
    const size_t qkvbase = (size_t)b * 12 * H3_ + h * 96;

    for (int i = tid; i < 12 * 96; i += 128) {
        int t = i / 96, d = i % 96;
        size_t o = qkvbase + (size_t)t * H3_ + d;
        q[t][d] = g_QKV[o];
        k[t][d] = g_QKV[o + H_];
        v[t][d] = g_QKV[o + 2 * H_];
    }
    __syncthreads();
    const int L = g_len[b];

    for (int p = tid; p < 144; p += 128) {
        int qi = p / 12, ki = p % 12;
        float s = 0.f;
#pragma unroll
        for (int d = 0; d < 96; d++) s += q[qi][d] * k[ki][d];
        sc[qi][ki] = (ki < L) ? s * 0.10206207261596577f : -1e9f;
    }
    __syncthreads();

    if (tid < 12) {
        float m = -3.0e38f;
        for (int j = 0; j < 12; j++) m = fmaxf(m, sc[tid][j]);
        float sum = 0.f;
        for (int j = 0; j < 12; j++) { float e = expf(sc[tid][j] - m); sc[tid][j] = e; sum += e; }
        float r = 1.f / sum;
        for (int j = 0; j < 12; j++) sc[tid][j] *= r;
    }
    __syncthreads();

    const size_t pbase = (size_t)b * 12 * H_ + h * 96;
    for (int i = tid; i < 12 * 96; i += 128) {
        int qi = i / 96, d = i % 96;
        float o = 0.f;
#pragma unroll
        for (int j = 0; j < 12; j++) o += sc[qi][j] * v[j][d];
        g_Ph[pbase + (size_t)qi * H_ + d] = __float2half_rn(o);
    }
}

// ---------------------------------------------------------------------------
// Row LayerNorm over H=768 (one CTA per row, 256 threads). Dual output.
// ---------------------------------------------------------------------------
__global__ void ln_kernel(const float* __restrict__ X,
                          const float* __restrict__ gam,
                          const float* __restrict__ bet,
                          float* __restrict__ Of, __half* __restrict__ Oh) {
    const int row = blockIdx.x;
    const int tid = threadIdx.x; // 256
    const float* x = X + (size_t)row * H_;
    float vals[3];
    float s = 0.f, s2 = 0.f;
#pragma unroll
    for (int i = 0; i < 3; i++) {
        float t = x[tid + i * 256];
        vals[i] = t; s += t; s2 += t * t;
    }
    __shared__ float red[2][8];
    s  = warp_red(s);
    s2 = warp_red(s2);
    if ((tid & 31) == 0) { red[0][tid >> 5] = s; red[1][tid >> 5] = s2; }
    __syncthreads();
    float ts = 0.f, ts2 = 0.f;
#pragma unroll
    for (int w = 0; w < 8; w++) { ts += red[0][w]; ts2 += red[1][w]; }
    const float mu  = ts * (1.f / 768.f);
    const float var = ts2 * (1.f / 768.f) - mu * mu;
    const float inv = rsqrtf(var + 1e-5f);
#pragma unroll
    for (int i = 0; i < 3; i++) {
        int c = tid + i * 256;
        float r = (vals[i] - mu) * inv * gam[c] + bet[c];
        if (Of) Of[(size_t)row * H_ + c] = r;
        if (Oh) Oh[(size_t)row * H_ + c] = __float2half_rn(r);
    }
}

// ---------------------------------------------------------------------------
// Final: x_g pool, 3-way gate softmax, output mix. One CTA per batch elem.
// ---------------------------------------------------------------------------
__global__ void final_kernel(const float* __restrict__ Wg,
                             const float* __restrict__ bg,
                             float* __restrict__ out) {
    const int b = blockIdx.x, tid = threadIdx.x; // 256
    const int L = g_len[b];
    const float invL = 1.f / (float)L;
    float xd[3], xl[3], xg[3];
    float p0 = 0.f, p1 = 0.f, p2 = 0.f;
#pragma unroll
    for (int i = 0; i < 3; i++) {
        int c = tid + i * 256;
        size_t bo = (size_t)b * H_ + c;
        xd[i] = g_xd[bo];
        xl[i] = g_xl[bo];
        float s = 0.f;
        for (int t = 0; t < L; t++)
            s += g_X2[((size_t)(b * 12 + t)) * H_ + c];
        xg[i] = s * invL;
        p0 += xd[i] * Wg[c * 3 + 0] + xl[i] * Wg[(768 + c) * 3 + 0] + xg[i] * Wg[(1536 + c) * 3 + 0];
        p1 += xd[i] * Wg[c * 3 + 1] + xl[i] * Wg[(768 + c) * 3 + 1] + xg[i] * Wg[(1536 + c) * 3 + 1];
        p2 += xd[i] * Wg[c * 3 + 2] + xl[i] * Wg[(768 + c) * 3 + 2] + xg[i] * Wg[(1536 + c) * 3 + 2];
    }
    p0 = warp_red(p0); p1 = warp_red(p1); p2 = warp_red(p2);
    __shared__ float red[8][3];
    if ((tid & 31) == 0) { red[tid >> 5][0] = p0; red[tid >> 5][1] = p1; red[tid >> 5][2] = p2; }
    __syncthreads();
    float l0 = bg[0], l1 = bg[1], l2 = bg[2];
#pragma unroll
    for (int w = 0; w < 8; w++) { l0 += red[w][0]; l1 += red[w][1]; l2 += red[w][2]; }
    float m  = fmaxf(l0, fmaxf(l1, l2));
    float e0 = expf(l0 - m), e1 = expf(l1 - m), e2 = expf(l2 - m);
    float rs = 1.f / (e0 + e1 + e2);
    float g0 = e0 * rs, g1 = e1 * rs, g2 = e2 * rs;
#pragma unroll
    for (int i = 0; i < 3; i++) {
        int c = tid + i * 256;
        out[(size_t)b * H_ + c] = g0 * xd[i] + g1 * xl[i] + g2 * xg[i];
    }
}

// ---------------------------------------------------------------------------
// Launch
// ---------------------------------------------------------------------------
extern "C" void kernel_launch(void* const* d_in, const int* in_sizes, int n_in,
                              void* d_out, int out_size) {
    const float* z_k  = (const float*)d_in[0];
    const float* ctx  = (const float*)d_in[1];
    const int*   mask = (const int*)  d_in[2];
    const int*   bidx = (const int*)  d_in[3];
    const float* Wq = (const float*)d_in[4];  const float* bq = (const float*)d_in[5];
    const float* Wk = (const float*)d_in[6];  const float* bk = (const float*)d_in[7];
    const float* Wv = (const float*)d_in[8];  const float* bv = (const float*)d_in[9];
    const float* Wo = (const float*)d_in[10]; const float* bo = (const float*)d_in[11];
    const float* ln1g = (const float*)d_in[12]; const float* ln1b = (const float*)d_in[13];
    const float* W1 = (const float*)d_in[14]; const float* b1 = (const float*)d_in[15];
    const float* W2 = (const float*)d_in[16]; const float* b2 = (const float*)d_in[17];
    const float* ln2g = (const float*)d_in[18]; const float* ln2b = (const float*)d_in[19];
    const float* Wd = (const float*)d_in[20]; const float* bd = (const float*)d_in[21];
    const float* Wl = (const float*)d_in[22]; const float* bl = (const float*)d_in[23];
    const float* Wg = (const float*)d_in[24]; const float* bg = (const float*)d_in[25];
    float* out = (float*)d_out;

    static bool attr_done = false;
    const int dynSmem = NSTG * STAGE;
    if (!attr_done) {
        cudaFuncSetAttribute(gemm_f16, cudaFuncAttributeMaxDynamicSharedMemorySize, dynSmem);
        attr_done = true;
    }

    void *pgf, *pgh, *pqkv, *pph, *py, *px1f, *px1h, *pffh, *px2;
    void *plph, *pzh, *pxd, *pxl, *pwh, *pbqkv;
    cudaGetSymbolAddress(&pgf,  g_gseqf);  cudaGetSymbolAddress(&pgh,  g_gseqh);
    cudaGetSymbolAddress(&pqkv, g_QKV);    cudaGetSymbolAddress(&pph,  g_Ph);
    cudaGetSymbolAddress(&py,   g_Y);      cudaGetSymbolAddress(&px1f, g_X1f);
    cudaGetSymbolAddress(&px1h, g_X1h);    cudaGetSymbolAddress(&pffh, g_FFh);
    cudaGetSymbolAddress(&px2,  g_X2);     cudaGetSymbolAddress(&plph, g_lph);
    cudaGetSymbolAddress(&pzh,  g_zh);     cudaGetSymbolAddress(&pxd,  g_xd);
    cudaGetSymbolAddress(&pxl,  g_xl);     cudaGetSymbolAddress(&pwh,  g_Wh);
    cudaGetSymbolAddress(&pbqkv, g_bqkv);

    float*  fgf  = (float*)pgf;    __half* fgh  = (__half*)pgh;
    float*  fqkv = (float*)pqkv;   __half* fph  = (__half*)pph;
    float*  fy   = (float*)py;     float*  fx1f = (float*)px1f;
    __half* fx1h = (__half*)px1h;  __half* fffh = (__half*)pffh;
    float*  fx2  = (float*)px2;    __half* flph = (__half*)plph;
    __half* fzh  = (__half*)pzh;   float*  fxd  = (float*)pxd;
    float*  fxl  = (float*)pxl;    __half* fwh  = (__half*)pwh;
    float*  fbqkv = (float*)pbqkv;

    // Weight / bias prep (fp16, [K][N] row-major, QKV fused)
    const int nHH = H_ * H_;
    pack_qkv<<<(nHH + 255) / 256, 256>>>(Wq, Wk, Wv, fwh + OFF_QKV);
    convh<<<(nHH + 255) / 256, 256>>>(Wo, fwh + OFF_WO, nHH);
    convh<<<(H_ * FF_ + 255) / 256, 256>>>(W1, fwh + OFF_W1, H_ * FF_);
    convh<<<(FF_ * H_ + 255) / 256, 256>>>(W2, fwh + OFF_W2, FF_ * H_);
    convh<<<(nHH + 255) / 256, 256>>>(Wd, fwh + OFF_WD, nHH);
    convh<<<(nHH + 255) / 256, 256>>>(Wl, fwh + OFF_WL, nHH);
    pack_bias<<<(H_ + 255) / 256, 256>>>(bq, bk, bv, fbqkv);

    gather_kernel<<<B_, 128>>>(z_k, ctx, mask, bidx);

    // Fused QKV projection (N = 2304)
    gemm_f16<<<dim3(H3_ / 128, MR_ / 128), 256, dynSmem>>>(
        fgh, fwh + OFF_QKV, fbqkv, nullptr, fqkv, MR_, H3_, H_, 0);
    // Attention
    attn_kernel<<<dim3(B_, 8), 128>>>();
    // Output projection + residual (gseq fp32), LN1
    gemm_f16<<<dim3(H_ / 128, MR_ / 128), 256, dynSmem>>>(
        fph, fwh + OFF_WO, bo, fgf, fy, MR_, H_, H_, 1);
    ln_kernel<<<MR_, 256>>>(fy, ln1g, ln1b, fx1f, fx1h);
    // FFN
    gemm_f16<<<dim3(FF_ / 128, MR_ / 128), 256, dynSmem>>>(
        fx1h, fwh + OFF_W1, b1, nullptr, fffh, MR_, FF_, H_, 2);
    gemm_f16<<<dim3(H_ / 128, MR_ / 128), 256, dynSmem>>>(
        fffh, fwh + OFF_W2, b2, fx1f, fy, MR_, H_, FF_, 1);
    ln_kernel<<<MR_, 256>>>(fy, ln2g, ln2b, fx2, nullptr);
    // Direct & local paths
    gemm_f16<<<dim3(H_ / 128, B_ / 128), 256, dynSmem>>>(
        fzh, fwh + OFF_WD, bd, nullptr, fxd, B_, H_, H_, 3);
    gemm_f16<<<dim3(H_ / 128, B_ / 128), 256, dynSmem>>>(
        flph, fwh + OFF_WL, bl, nullptr, fxl, B_, H_, H_, 3);
    // Gate + output
    final_kernel<<<B_, 256>>>(Wg, bg, out);
}

// round 5
// speedup vs baseline: 3.3766x; 1.5991x over previous
#include <cuda_runtime.h>
#include <cuda_fp16.h>
#include <math.h>
#include <stdint.h>

// ---------------------------------------------------------------------------
// Problem constants
// ---------------------------------------------------------------------------
constexpr int B_   = 8192;
constexpr int H_   = 768;
constexpr int H3_  = 2304;
constexpr int FF_  = 2048;
constexpr int MR_  = B_ * 12;   // max flattened rows (uncompacted bound)

// ---------------------------------------------------------------------------
// Scratch (static device globals) — compacted token-major layout
// ---------------------------------------------------------------------------
__device__ __align__(256) float  g_gseqf[(size_t)MR_ * H_];
__device__ __align__(256) __half g_gseqh[(size_t)MR_ * H_];
__device__ __align__(256) float  g_QKV [(size_t)MR_ * H3_];
__device__ __align__(256) __half g_Ph  [(size_t)MR_ * H_];
__device__ __align__(256) float  g_Y   [(size_t)MR_ * H_];
__device__ __align__(256) float  g_X1f [(size_t)MR_ * H_];
__device__ __align__(256) __half g_X1h [(size_t)MR_ * H_];
__device__ __align__(256) __half g_FFh [(size_t)MR_ * FF_];
__device__ __align__(256) float  g_X2  [(size_t)MR_ * H_];
__device__ __align__(256) __half g_lph [(size_t)B_ * H_];
__device__ __align__(256) __half g_zh  [(size_t)B_ * H_];
__device__ __align__(256) float  g_xd  [(size_t)B_ * H_];
__device__ __align__(256) float  g_xl  [(size_t)B_ * H_];
__device__ int   g_len[B_];     // live rows per batch (hlen + 1)
__device__ int   g_off[B_];     // exclusive prefix of g_len
__device__ int   g_Mtot;        // total live rows
__device__ float g_bqkv[H3_];

// Half weight arena ([K][N] row-major, NOT transposed)
constexpr size_t OFF_QKV = 0;                                  // [768][2304]
constexpr size_t OFF_WO  = OFF_QKV + (size_t)H_ * H3_;         // [768][768]
constexpr size_t OFF_W1  = OFF_WO  + (size_t)H_ * H_;          // [768][2048]
constexpr size_t OFF_W2  = OFF_W1  + (size_t)H_ * FF_;         // [2048][768]
constexpr size_t OFF_WD  = OFF_W2  + (size_t)FF_ * H_;         // [768][768]
constexpr size_t OFF_WL  = OFF_WD  + (size_t)H_ * H_;          // [768][768]
__device__ __align__(256) __half g_Wh[OFF_WL + (size_t)H_ * H_];

// ---------------------------------------------------------------------------
// Helpers
// ---------------------------------------------------------------------------
__device__ __forceinline__ void cpasync16(uint32_t saddr, const void* g) {
    asm volatile("cp.async.cg.shared.global [%0], [%1], 16;\n" :: "r"(saddr), "l"(g));
}
__device__ __forceinline__ float warp_red(float v) {
#pragma unroll
    for (int o = 16; o > 0; o >>= 1) v += __shfl_xor_sync(0xffffffffu, v, o);
    return v;
}
__device__ __forceinline__ void ldsm4(uint32_t* r, uint32_t addr) {
    asm volatile("ldmatrix.sync.aligned.m8n8.x4.shared.b16 {%0,%1,%2,%3}, [%4];\n"
                 : "=r"(r[0]), "=r"(r[1]), "=r"(r[2]), "=r"(r[3]) : "r"(addr));
}
__device__ __forceinline__ void ldsm4t(uint32_t* r, uint32_t addr) {
    asm volatile("ldmatrix.sync.aligned.m8n8.x4.trans.shared.b16 {%0,%1,%2,%3}, [%4];\n"
                 : "=r"(r[0]), "=r"(r[1]), "=r"(r[2]), "=r"(r[3]) : "r"(addr));
}
__device__ __forceinline__ void mma16816(float* c, const uint32_t* a, uint32_t b0, uint32_t b1) {
    asm volatile(
        "mma.sync.aligned.m16n8k16.row.col.f32.f16.f16.f32 "
        "{%0,%1,%2,%3}, {%4,%5,%6,%7}, {%8,%9}, {%0,%1,%2,%3};\n"
        : "+f"(c[0]), "+f"(c[1]), "+f"(c[2]), "+f"(c[3])
        : "r"(a[0]), "r"(a[1]), "r"(a[2]), "r"(a[3]), "r"(b0), "r"(b1));
}

// ---------------------------------------------------------------------------
// Weight prep
// ---------------------------------------------------------------------------
__global__ void pack_qkv(const float* __restrict__ Wq, const float* __restrict__ Wk,
                         const float* __restrict__ Wv, __half* __restrict__ dst) {
    int i = blockIdx.x * 256 + threadIdx.x;
    if (i >= H_ * H_) return;
    int r = i / H_, c = i % H_;
    size_t o = (size_t)r * H3_ + c;
    dst[o]          = __float2half_rn(Wq[i]);
    dst[o + H_]     = __float2half_rn(Wk[i]);
    dst[o + 2 * H_] = __float2half_rn(Wv[i]);
}
__global__ void convh(const float* __restrict__ src, __half* __restrict__ dst, int n) {
    int i = blockIdx.x * 256 + threadIdx.x;
    if (i < n) dst[i] = __float2half_rn(src[i]);
}
__global__ void pack_bias(const float* __restrict__ bq, const float* __restrict__ bk,
                          const float* __restrict__ bv, float* __restrict__ dst) {
    int i = threadIdx.x + blockIdx.x * 256;
    if (i < H_) { dst[i] = bq[i]; dst[i + H_] = bk[i]; dst[i + 2 * H_] = bv[i]; }
}

// ---------------------------------------------------------------------------
// Compaction bookkeeping
// ---------------------------------------------------------------------------
__global__ void len_kernel(const int* __restrict__ mask) {
    int b = blockIdx.x * 256 + threadIdx.x;
    if (b >= B_) return;
    int cnt = 0;
#pragma unroll
    for (int s = 0; s < 12; s++) cnt += (mask[b * 12 + s] != 0);
    int hlen = cnt < 11 ? cnt : 11;
    g_len[b] = hlen + 1;
}

__global__ void scan_kernel() {  // single block, 1024 threads, 8 items each
    __shared__ int sm[1024];
    const int t = threadIdx.x;
    int loc[8];
    int s = 0;
#pragma unroll
    for (int i = 0; i < 8; i++) { loc[i] = s; s += g_len[t * 8 + i]; }
    sm[t] = s;
    __syncthreads();
    for (int off = 1; off < 1024; off <<= 1) {
        int v = (t >= off) ? sm[t - off] : 0;
        __syncthreads();
        sm[t] += v;
        __syncthreads();
    }
    const int base = (t > 0) ? sm[t - 1] : 0;
#pragma unroll
    for (int i = 0; i < 8; i++) g_off[t * 8 + i] = base + loc[i];
    if (t == 1023) g_Mtot = sm[1023];
}

// ---------------------------------------------------------------------------
// Gather: compacted gseq (fp32 + half), lpool (half), z (half).
// CRITICAL (reference pad-mask quirk): the last live row (index hlen) is a
// ZERO row when hlen < 11 — z_k only enters the sequence when hlen == 11.
// ---------------------------------------------------------------------------
__global__ void gather_kernel(const float* __restrict__ z_k,
                              const float* __restrict__ buf,
                              const int*   __restrict__ mask,
                              const int*   __restrict__ bidx) {
    const int b = blockIdx.x;
    const int tid = threadIdx.x; // 128
    __shared__ int ord[12];
    __shared__ int s_nv;
    if (tid == 0) {
        int idx = bidx[b];
        int cnt = 0;
        for (int a = 11; a >= 0; a--) {
            int s = (idx - a + 24) % 12;
            if (mask[b * 12 + s]) ord[cnt++] = s;
        }
        s_nv = cnt;
    }
    __syncthreads();
    const int nv = s_nv;
    const int hlen = nv < 11 ? nv : 11;
    const int off = g_off[b];
    const float* zb = z_k + (size_t)b * H_;

    for (int t = 0; t < hlen; t++) {
        size_t doff = (size_t)(off + t) * H_;
        const float* src = buf + ((size_t)(b * 12 + ord[t])) * H_;
        for (int i = tid; i < H_; i += 128) {
            float v = src[i];
            g_gseqf[doff + i] = v;
            g_gseqh[doff + i] = __float2half_rn(v);
        }
    }
    {
        // Last live row: z_k only when the history is full (hlen == 11);
        // otherwise the reference's valid window ends with a zero row.
        size_t doff = (size_t)(off + hlen) * H_;
        if (hlen == 11) {
            for (int i = tid; i < H_; i += 128) {
                float v = zb[i];
                g_gseqf[doff + i] = v;
                g_gseqh[doff + i] = __float2half_rn(v);
            }
        } else {
            for (int i = tid; i < H_; i += 128) {
                g_gseqf[doff + i] = 0.f;
                g_gseqh[doff + i] = __half(0.f);
            }
        }
    }

    const int c4 = nv < 4 ? nv : 4;
    const float inv = 1.f / (float)(c4 + 1);
    for (int i = tid; i < H_; i += 128) {
        float s = 0.f;
        for (int t = 0; t < c4; t++)
            s += buf[((size_t)(b * 12 + ord[t])) * H_ + i];
        if (c4 == 4) s += zb[i];
        g_lph[(size_t)b * H_ + i] = __float2half_rn(s * inv);
        g_zh [(size_t)b * H_ + i] = __float2half_rn(zb[i]);
    }
}

// ---------------------------------------------------------------------------
// fp16 tensor-core GEMM (128x128x32 tiles, 4-stage cp.async, ldmatrix+mma).
//   If dynM != 0, CTAs whose M-tile starts beyond g_Mtot exit early.
//   epi: 0 fp32 out, 1 fp32 out + resid, 2 relu -> half out, 3 tanh fp32 out
// ---------------------------------------------------------------------------
#define NSTG 4
constexpr int A_STRIDE_B = 80;
constexpr int B_STRIDE_B = 272;
constexpr int A_BYTES = 128 * A_STRIDE_B;  // 10240
constexpr int B_BYTES = 32 * B_STRIDE_B;   // 8704
constexpr int STAGE   = A_BYTES + B_BYTES; // 18944

__global__ void __launch_bounds__(256, 2)
gemm_f16(const __half* __restrict__ A, const __half* __restrict__ W,
         const float* __restrict__ bias, const float* __restrict__ resid,
         void* __restrict__ Cout, int N, int K, int epi, int dynM)
{
    const int bn = blockIdx.x, bm = blockIdx.y;
    if (dynM && bm * 128 >= g_Mtot) return;

    extern __shared__ __align__(16) char smc[];
    const int tid = threadIdx.x, wid = tid >> 5, lane = tid & 31;
    const int wm = (wid & 1) * 64;
    const int wn = (wid >> 1) * 32;

    const uint32_t sbase = (uint32_t)__cvta_generic_to_shared(smc);
    const __half* Ab = A + (size_t)(bm * 128) * K;

    float acc[4][4][4];
#pragma unroll
    for (int mi = 0; mi < 4; mi++)
#pragma unroll
        for (int ni = 0; ni < 4; ni++)
#pragma unroll
            for (int r = 0; r < 4; r++) acc[mi][ni][r] = 0.f;

    auto load_stage = [&](int s, int kt) {
        uint32_t as = sbase + s * STAGE;
        uint32_t bs = as + A_BYTES;
        const __half* Ak = Ab + kt * 32;
        const __half* Wk = W + (size_t)(kt * 32) * N + bn * 128;
#pragma unroll
        for (int i = 0; i < 2; i++) {
            int idx = tid + (i << 8);
            int r = idx >> 2, c = idx & 3;
            cpasync16(as + r * A_STRIDE_B + c * 16, Ak + (size_t)r * K + c * 8);
        }
#pragma unroll
        for (int i = 0; i < 2; i++) {
            int idx = tid + (i << 8);
            int r = idx >> 4, c = idx & 15;
            cpasync16(bs + r * B_STRIDE_B + c * 16, Wk + (size_t)r * N + c * 8);
        }
        asm volatile("cp.async.commit_group;\n" ::: "memory");
    };

    const int NIT = K >> 5;
#pragma unroll
    for (int s = 0; s < NSTG - 1; s++) load_stage(s, s);

    const int l15 = lane & 15;
    const int l16 = (lane >> 4) << 3;

    for (int it = 0; it < NIT; it++) {
        asm volatile("cp.async.wait_group %0;\n" :: "n"(NSTG - 2) : "memory");
        __syncthreads();
        if (it + NSTG - 1 < NIT) load_stage((it + NSTG - 1) & (NSTG - 1), it + NSTG - 1);
        else asm volatile("cp.async.commit_group;\n" ::: "memory");

        const int s = it & (NSTG - 1);
        const uint32_t as = sbase + s * STAGE;
        const uint32_t bs = as + A_BYTES;
#pragma unroll
        for (int kh = 0; kh < 2; kh++) {
            const int kc = kh * 16;
            uint32_t a[4][4], b[2][4];
#pragma unroll
            for (int mi = 0; mi < 4; mi++)
                ldsm4(a[mi], as + (wm + mi * 16 + l15) * A_STRIDE_B + (kc + l16) * 2);
#pragma unroll
            for (int np = 0; np < 2; np++)
                ldsm4t(b[np], bs + (kc + l15) * B_STRIDE_B + (wn + np * 16 + l16) * 2);
#pragma unroll
            for (int mi = 0; mi < 4; mi++)
#pragma unroll
                for (int ni = 0; ni < 4; ni++)
                    mma16816(acc[mi][ni], a[mi],
                             b[ni >> 1][(ni & 1) * 2], b[ni >> 1][(ni & 1) * 2 + 1]);
        }
    }

    const int g = lane >> 2, tg = lane & 3;
    const int row0 = bm * 128 + wm;
    const int col0 = bn * 128 + wn;
#pragma unroll
    for (int mi = 0; mi < 4; mi++) {
#pragma unroll
        for (int ni = 0; ni < 4; ni++) {
            const int c = col0 + ni * 8 + tg * 2;
            float2 bv = *(const float2*)(bias + c);
#pragma unroll
            for (int hh = 0; hh < 2; hh++) {
                const int r = row0 + mi * 16 + g + hh * 8;
                float v0 = acc[mi][ni][hh * 2]     + bv.x;
                float v1 = acc[mi][ni][hh * 2 + 1] + bv.y;
                const size_t off = (size_t)r * N + c;
                if (epi == 1) {
                    float2 rv = *(const float2*)(resid + off);
                    v0 += rv.x; v1 += rv.y;
                    *(float2*)((float*)Cout + off) = make_float2(v0, v1);
                } else if (epi == 2) {
                    v0 = fmaxf(v0, 0.f); v1 = fmaxf(v1, 0.f);
                    *(__half2*)((__half*)Cout + off) = __floats2half2_rn(v0, v1);
                } else if (epi == 3) {
                    *(float2*)((float*)Cout + off) = make_float2(tanhf(v0), tanhf(v1));
                } else {
                    *(float2*)((float*)Cout + off) = make_float2(v0, v1);
                }
            }
        }
    }
}

// ---------------------------------------------------------------------------
// Attention on compacted rows: one CTA per (batch, head), L = g_len[b] rows.
// All L rows are valid keys (the quirk zero-row included), so no key mask.
// ---------------------------------------------------------------------------
__global__ void attn_kernel() {
    const int b = blockIdx.x, h = blockIdx.y;
    __shared__ float q[12][97], k[12][97], v[12][97];
    __shared__ float sc[12][12];
    const int tid = threadIdx.x; // 128
    const int L = g_len[b];
    const int off = g_off[b];
    const size_t qkvbase = (size_t)off * H3_ + h * 96;

    for (int i = tid; i < L * 96; i += 128) {
        int t = i / 96, d = i % 96;
        size_t o = qkvbase + (size_t)t * H3_ + d;
        q[t][d] = g_QKV[o];
        k[t][d] = g_QKV[o + H_];
        v[t][d] = g_QKV[o + 2 * H_];
    }
    __syncthreads();

    for (int p = tid; p < L * L; p += 128) {
        int qi = p / L, ki = p % L;
        float s = 0.f;
#pragma unroll
        for (int d = 0; d < 96; d++) s += q[qi][d] * k[ki][d];
        sc[qi][ki] = s * 0.10206207261596577f;
    }
    __syncthreads();

    if (tid < L) {
        float m = -3.0e38f;
        for (int j = 0; j < L; j++) m = fmaxf(m, sc[tid][j]);
        float sum = 0.f;
        for (int j = 0; j < L; j++) { float e = expf(sc[tid][j] - m); sc[tid][j] = e; sum += e; }
        float r = 1.f / sum;
        for (int j = 0; j < L; j++) sc[tid][j] *= r;
    }
    __syncthreads();

    const size_t pbase = (size_t)off * H_ + h * 96;
    for (int i = tid; i < L * 96; i += 128) {
        int qi = i / 96, d = i % 96;
        float o = 0.f;
        for (int j = 0; j < L; j++) o += sc[qi][j] * v[j][d];
        g_Ph[pbase + (size_t)qi * H_ + d] = __float2half_rn(o);
    }
}

// ---------------------------------------------------------------------------
// Row LayerNorm over H=768 (one CTA per row). Early exit beyond g_Mtot.
// ---------------------------------------------------------------------------
__global__ void ln_kernel(const float* __restrict__ X,
                          const float* __restrict__ gam,
                          const float* __restrict__ bet,
                          float* __restrict__ Of, __half* __restrict__ Oh) {
    const int row = blockIdx.x;
    if (row >= g_Mtot) return;
    const int tid = threadIdx.x; // 256
    const float* x = X + (size_t)row * H_;
    float vals[3];
    float s = 0.f, s2 = 0.f;
#pragma unroll
    for (int i = 0; i < 3; i++) {
        float t = x[tid + i * 256];
        vals[i] = t; s += t; s2 += t * t;
    }
    __shared__ float red[2][8];
    s  = warp_red(s);
    s2 = warp_red(s2);
    if ((tid & 31) == 0) { red[0][tid >> 5] = s; red[1][tid >> 5] = s2; }
    __syncthreads();
    float ts = 0.f, ts2 = 0.f;
#pragma unroll
    for (int w = 0; w < 8; w++) { ts += red[0][w]; ts2 += red[1][w]; }
    const float mu  = ts * (1.f / 768.f);
    const float var = ts2 * (1.f / 768.f) - mu * mu;
    const float inv = rsqrtf(var + 1e-5f);
#pragma unroll
    for (int i = 0; i < 3; i++) {
        int c = tid + i * 256;
        float r = (vals[i] - mu) * inv * gam[c] + bet[c];
        if (Of) Of[(size_t)row * H_ + c] = r;
        if (Oh) Oh[(size_t)row * H_ + c] = __float2half_rn(r);
    }
}

// ---------------------------------------------------------------------------
// Final: x_g pool over compacted rows, 3-way gate softmax, output mix.
// ---------------------------------------------------------------------------
__global__ void final_kernel(const float* __restrict__ Wg,
                             const float* __restrict__ bg,
                             float* __restrict__ out) {
    const int b = blockIdx.x, tid = threadIdx.x; // 256
    const int L = g_len[b];
    const int off = g_off[b];
    const float invL = 1.f / (float)L;
    float xd[3], xl[3], xg[3];
    float p0 = 0.f, p1 = 0.f, p2 = 0.f;
#pragma unroll
    for (int i = 0; i < 3; i++) {
        int c = tid + i * 256;
        size_t bo = (size_t)b * H_ + c;
        xd[i] = g_xd[bo];
        xl[i] = g_xl[bo];
        float s = 0.f;
        for (int t = 0; t < L; t++)
            s += g_X2[(size_t)(off + t) * H_ + c];
        xg[i] = s * invL;
        p0 += xd[i] * Wg[c * 3 + 0] + xl[i] * Wg[(768 + c) * 3 + 0] + xg[i] * Wg[(1536 + c) * 3 + 0];
        p1 += xd[i] * Wg[c * 3 + 1] + xl[i] * Wg[(768 + c) * 3 + 1] + xg[i] * Wg[(1536 + c) * 3 + 1];
        p2 += xd[i] * Wg[c * 3 + 2] + xl[i] * Wg[(768 + c) * 3 + 2] + xg[i] * Wg[(1536 + c) * 3 + 2];
    }
    p0 = warp_red(p0); p1 = warp_red(p1); p2 = warp_red(p2);
    __shared__ float red[8][3];
    if ((tid & 31) == 0) { red[tid >> 5][0] = p0; red[tid >> 5][1] = p1; red[tid >> 5][2] = p2; }
    __syncthreads();
    float l0 = bg[0], l1 = bg[1], l2 = bg[2];
#pragma unroll
    for (int w = 0; w < 8; w++) { l0 += red[w][0]; l1 += red[w][1]; l2 += red[w][2]; }
    float m  = fmaxf(l0, fmaxf(l1, l2));
    float e0 = expf(l0 - m), e1 = expf(l1 - m), e2 = expf(l2 - m);
    float rs = 1.f / (e0 + e1 + e2);
    float g0 = e0 * rs, g1 = e1 * rs, g2 = e2 * rs;
#pragma unroll
    for (int i = 0; i < 3; i++) {
        int c = tid + i * 256;
        out[(size_t)b * H_ + c] = g0 * xd[i] + g1 * xl[i] + g2 * xg[i];
    }
}

// ---------------------------------------------------------------------------
// Launch
// ---------------------------------------------------------------------------
extern "C" void kernel_launch(void* const* d_in, const int* in_sizes, int n_in,
                              void* d_out, int out_size) {
    const float* z_k  = (const float*)d_in[0];
    const float* ctx  = (const float*)d_in[1];
    const int*   mask = (const int*)  d_in[2];
    const int*   bidx = (const int*)  d_in[3];
    const float* Wq = (const float*)d_in[4];  const float* bq = (const float*)d_in[5];
    const float* Wk = (const float*)d_in[6];  const float* bk = (const float*)d_in[7];
    const float* Wv = (const float*)d_in[8];  const float* bv = (const float*)d_in[9];
    const float* Wo = (const float*)d_in[10]; const float* bo = (const float*)d_in[11];
    const float* ln1g = (const float*)d_in[12]; const float* ln1b = (const float*)d_in[13];
    const float* W1 = (const float*)d_in[14]; const float* b1 = (const float*)d_in[15];
    const float* W2 = (const float*)d_in[16]; const float* b2 = (const float*)d_in[17];
    const float* ln2g = (const float*)d_in[18]; const float* ln2b = (const float*)d_in[19];
    const float* Wd = (const float*)d_in[20]; const float* bd = (const float*)d_in[21];
    const float* Wl = (const float*)d_in[22]; const float* bl = (const float*)d_in[23];
    const float* Wg = (const float*)d_in[24]; const float* bg = (const float*)d_in[25];
    float* out = (float*)d_out;

    static bool attr_done = false;
    const int dynSmem = NSTG * STAGE;
    if (!attr_done) {
        cudaFuncSetAttribute(gemm_f16, cudaFuncAttributeMaxDynamicSharedMemorySize, dynSmem);
        attr_done = true;
    }

    void *pgf, *pgh, *pqkv, *pph, *py, *px1f, *px1h, *pffh, *px2;
    void *plph, *pzh, *pxd, *pxl, *pwh, *pbqkv;
    cudaGetSymbolAddress(&pgf,  g_gseqf);  cudaGetSymbolAddress(&pgh,  g_gseqh);
    cudaGetSymbolAddress(&pqkv, g_QKV);    cudaGetSymbolAddress(&pph,  g_Ph);
    cudaGetSymbolAddress(&py,   g_Y);      cudaGetSymbolAddress(&px1f, g_X1f);
    cudaGetSymbolAddress(&px1h, g_X1h);    cudaGetSymbolAddress(&pffh, g_FFh);
    cudaGetSymbolAddress(&px2,  g_X2);     cudaGetSymbolAddress(&plph, g_lph);
    cudaGetSymbolAddress(&pzh,  g_zh);     cudaGetSymbolAddress(&pxd,  g_xd);
    cudaGetSymbolAddress(&pxl,  g_xl);     cudaGetSymbolAddress(&pwh,  g_Wh);
    cudaGetSymbolAddress(&pbqkv, g_bqkv);

    float*  fgf  = (float*)pgf;    __half* fgh  = (__half*)pgh;
    float*  fqkv = (float*)pqkv;   __half* fph  = (__half*)pph;
    float*  fy   = (float*)py;     float*  fx1f = (float*)px1f;
    __half* fx1h = (__half*)px1h;  __half* fffh = (__half*)pffh;
    float*  fx2  = (float*)px2;    __half* flph = (__half*)plph;
    __half* fzh  = (__half*)pzh;   float*  fxd  = (float*)pxd;
    float*  fxl  = (float*)pxl;    __half* fwh  = (__half*)pwh;
    float*  fbqkv = (float*)pbqkv;

    // Weight / bias prep (fp16, [K][N] row-major, QKV fused)
    const int nHH = H_ * H_;
    pack_qkv<<<(nHH + 255) / 256, 256>>>(Wq, Wk, Wv, fwh + OFF_QKV);
    convh<<<(nHH + 255) / 256, 256>>>(Wo, fwh + OFF_WO, nHH);
    convh<<<(H_ * FF_ + 255) / 256, 256>>>(W1, fwh + OFF_W1, H_ * FF_);
    convh<<<(FF_ * H_ + 255) / 256, 256>>>(W2, fwh + OFF_W2, FF_ * H_);
    convh<<<(nHH + 255) / 256, 256>>>(Wd, fwh + OFF_WD, nHH);
    convh<<<(nHH + 255) / 256, 256>>>(Wl, fwh + OFF_WL, nHH);
    pack_bias<<<(H_ + 255) / 256, 256>>>(bq, bk, bv, fbqkv);

    // Compaction bookkeeping + gather
    len_kernel<<<(B_ + 255) / 256, 256>>>(mask);
    scan_kernel<<<1, 1024>>>();
    gather_kernel<<<B_, 128>>>(z_k, ctx, mask, bidx);

    // Fused QKV projection (N = 2304), compacted rows
    gemm_f16<<<dim3(H3_ / 128, MR_ / 128), 256, dynSmem>>>(
        fgh, fwh + OFF_QKV, fbqkv, nullptr, fqkv, H3_, H_, 0, 1);
    // Attention
    attn_kernel<<<dim3(B_, 8), 128>>>();
    // Output projection + residual (gseq fp32), LN1
    gemm_f16<<<dim3(H_ / 128, MR_ / 128), 256, dynSmem>>>(
        fph, fwh + OFF_WO, bo, fgf, fy, H_, H_, 1, 1);
    ln_kernel<<<MR_, 256>>>(fy, ln1g, ln1b, fx1f, fx1h);
    // FFN
    gemm_f16<<<dim3(FF_ / 128, MR_ / 128), 256, dynSmem>>>(
        fx1h, fwh + OFF_W1, b1, nullptr, fffh, FF_, H_, 2, 1);
    gemm_f16<<<dim3(H_ / 128, MR_ / 128), 256, dynSmem>>>(
        fffh, fwh + OFF_W2, b2, fx1f, fy, H_, FF_, 1, 1);
    ln_kernel<<<MR_, 256>>>(fy, ln2g, ln2b, fx2, nullptr);
    // Direct & local paths (full B_ rows, no compaction)
    gemm_f16<<<dim3(H_ / 128, B_ / 128), 256, dynSmem>>>(
        fzh, fwh + OFF_WD, bd, nullptr, fxd, H_, H_, 3, 0);
    gemm_f16<<<dim3(H_ / 128, B_ / 128), 256, dynSmem>>>(
        flph, fwh + OFF_WL, bl, nullptr, fxl, H_, H_, 3, 0);
    // Gate + output
    final_kernel<<<B_, 256>>>(Wg, bg, out);
}

// round 6
// speedup vs baseline: 3.5934x; 1.0642x over previous
#include <cuda_runtime.h>
#include <cuda_fp16.h>
#include <math.h>
#include <stdint.h>

// ---------------------------------------------------------------------------
// Problem constants
// ---------------------------------------------------------------------------
constexpr int B_   = 8192;
constexpr int H_   = 768;
constexpr int H3_  = 2304;
constexpr int FF_  = 2048;
constexpr int MR_  = B_ * 12;   // max flattened rows (uncompacted bound)

// ---------------------------------------------------------------------------
// Scratch (static device globals) — compacted token-major layout
// ---------------------------------------------------------------------------
__device__ __align__(256) float  g_gseqf[(size_t)MR_ * H_];
__device__ __align__(256) __half g_gseqh[(size_t)MR_ * H_];
__device__ __align__(256) __half g_QKVh[(size_t)MR_ * H3_];
__device__ __align__(256) __half g_Ph  [(size_t)MR_ * H_];
__device__ __align__(256) float  g_Y   [(size_t)MR_ * H_];
__device__ __align__(256) float  g_X1f [(size_t)MR_ * H_];
__device__ __align__(256) __half g_X1h [(size_t)MR_ * H_];
__device__ __align__(256) __half g_FFh [(size_t)MR_ * FF_];
__device__ __align__(256) __half g_zl  [(size_t)(2 * B_) * H_];  // rows [0,B): z, [B,2B): lpool
__device__ __align__(256) float  g_xdl [(size_t)(2 * B_) * H_];  // rows [0,B): x_d, [B,2B): x_l
__device__ int   g_len[B_];     // live rows per batch (hlen + 1)
__device__ int   g_off[B_];     // exclusive prefix of g_len
__device__ int   g_Mtot;        // total live rows
__device__ float g_bqkv[H3_];

// Half weight arena ([K][N] row-major, NOT transposed)
constexpr size_t OFF_QKV = 0;                                  // [768][2304]
constexpr size_t OFF_WO  = OFF_QKV + (size_t)H_ * H3_;         // [768][768]
constexpr size_t OFF_W1  = OFF_WO  + (size_t)H_ * H_;          // [768][2048]
constexpr size_t OFF_W2  = OFF_W1  + (size_t)H_ * FF_;         // [2048][768]
constexpr size_t OFF_WD  = OFF_W2  + (size_t)FF_ * H_;         // [768][768]
constexpr size_t OFF_WL  = OFF_WD  + (size_t)H_ * H_;          // [768][768]
__device__ __align__(256) __half g_Wh[OFF_WL + (size_t)H_ * H_];

// ---------------------------------------------------------------------------
// Helpers
// ---------------------------------------------------------------------------
__device__ __forceinline__ void cpasync16(uint32_t saddr, const void* g) {
    asm volatile("cp.async.cg.shared.global [%0], [%1], 16;\n" :: "r"(saddr), "l"(g));
}
__device__ __forceinline__ float warp_red(float v) {
#pragma unroll
    for (int o = 16; o > 0; o >>= 1) v += __shfl_xor_sync(0xffffffffu, v, o);
    return v;
}
__device__ __forceinline__ void ldsm4(uint32_t* r, uint32_t addr) {
    asm volatile("ldmatrix.sync.aligned.m8n8.x4.shared.b16 {%0,%1,%2,%3}, [%4];\n"
                 : "=r"(r[0]), "=r"(r[1]), "=r"(r[2]), "=r"(r[3]) : "r"(addr));
}
__device__ __forceinline__ void ldsm4t(uint32_t* r, uint32_t addr) {
    asm volatile("ldmatrix.sync.aligned.m8n8.x4.trans.shared.b16 {%0,%1,%2,%3}, [%4];\n"
                 : "=r"(r[0]), "=r"(r[1]), "=r"(r[2]), "=r"(r[3]) : "r"(addr));
}
__device__ __forceinline__ void mma16816(float* c, const uint32_t* a, uint32_t b0, uint32_t b1) {
    asm volatile(
        "mma.sync.aligned.m16n8k16.row.col.f32.f16.f16.f32 "
        "{%0,%1,%2,%3}, {%4,%5,%6,%7}, {%8,%9}, {%0,%1,%2,%3};\n"
        : "+f"(c[0]), "+f"(c[1]), "+f"(c[2]), "+f"(c[3])
        : "r"(a[0]), "r"(a[1]), "r"(a[2]), "r"(a[3]), "r"(b0), "r"(b1));
}

// ---------------------------------------------------------------------------
// Weight prep
// ---------------------------------------------------------------------------
__global__ void pack_qkv(const float* __restrict__ Wq, const float* __restrict__ Wk,
                         const float* __restrict__ Wv, __half* __restrict__ dst) {
    int i = blockIdx.x * 256 + threadIdx.x;
    if (i >= H_ * H_) return;
    int r = i / H_, c = i % H_;
    size_t o = (size_t)r * H3_ + c;
    dst[o]          = __float2half_rn(Wq[i]);
    dst[o + H_]     = __float2half_rn(Wk[i]);
    dst[o + 2 * H_] = __float2half_rn(Wv[i]);
}
__global__ void convh(const float* __restrict__ src, __half* __restrict__ dst, int n) {
    int i = blockIdx.x * 256 + threadIdx.x;
    if (i < n) dst[i] = __float2half_rn(src[i]);
}
__global__ void pack_bias(const float* __restrict__ bq, const float* __restrict__ bk,
                          const float* __restrict__ bv, float* __restrict__ dst) {
    int i = threadIdx.x + blockIdx.x * 256;
    if (i < H_) { dst[i] = bq[i]; dst[i + H_] = bk[i]; dst[i + 2 * H_] = bv[i]; }
}

// ---------------------------------------------------------------------------
// Compaction bookkeeping
// ---------------------------------------------------------------------------
__global__ void len_kernel(const int* __restrict__ mask) {
    int b = blockIdx.x * 256 + threadIdx.x;
    if (b >= B_) return;
    int cnt = 0;
#pragma unroll
    for (int s = 0; s < 12; s++) cnt += (mask[b * 12 + s] != 0);
    int hlen = cnt < 11 ? cnt : 11;
    g_len[b] = hlen + 1;
}

__global__ void scan_kernel() {  // single block, 1024 threads, 8 items each
    __shared__ int sm[1024];
    const int t = threadIdx.x;
    int loc[8];
    int s = 0;
#pragma unroll
    for (int i = 0; i < 8; i++) { loc[i] = s; s += g_len[t * 8 + i]; }
    sm[t] = s;
    __syncthreads();
    for (int off = 1; off < 1024; off <<= 1) {
        int v = (t >= off) ? sm[t - off] : 0;
        __syncthreads();
        sm[t] += v;
        __syncthreads();
    }
    const int base = (t > 0) ? sm[t - 1] : 0;
#pragma unroll
    for (int i = 0; i < 8; i++) g_off[t * 8 + i] = base + loc[i];
    if (t == 1023) g_Mtot = sm[1023];
}

// ---------------------------------------------------------------------------
// Gather: compacted gseq (fp32 + half), z/lpool stacked (half).
// Pad-mask quirk: last live row is ZERO unless hlen == 11 (then it's z_k).
// ---------------------------------------------------------------------------
__global__ void gather_kernel(const float* __restrict__ z_k,
                              const float* __restrict__ buf,
                              const int*   __restrict__ mask,
                              const int*   __restrict__ bidx) {
    const int b = blockIdx.x;
    const int tid = threadIdx.x; // 128
    __shared__ int ord[12];
    __shared__ int s_nv;
    if (tid == 0) {
        int idx = bidx[b];
        int cnt = 0;
        for (int a = 11; a >= 0; a--) {
            int s = (idx - a + 24) % 12;
            if (mask[b * 12 + s]) ord[cnt++] = s;
        }
        s_nv = cnt;
    }
    __syncthreads();
    const int nv = s_nv;
    const int hlen = nv < 11 ? nv : 11;
    const int off = g_off[b];
    const float* zb = z_k + (size_t)b * H_;

    for (int t = 0; t < hlen; t++) {
        size_t doff = (size_t)(off + t) * H_;
        const float* src = buf + ((size_t)(b * 12 + ord[t])) * H_;
        for (int i = tid; i < H_; i += 128) {
            float v = src[i];
            g_gseqf[doff + i] = v;
            g_gseqh[doff + i] = __float2half_rn(v);
        }
    }
    {
        size_t doff = (size_t)(off + hlen) * H_;
        if (hlen == 11) {
            for (int i = tid; i < H_; i += 128) {
                float v = zb[i];
                g_gseqf[doff + i] = v;
                g_gseqh[doff + i] = __float2half_rn(v);
            }
        } else {
            for (int i = tid; i < H_; i += 128) {
                g_gseqf[doff + i] = 0.f;
                g_gseqh[doff + i] = __half(0.f);
            }
        }
    }

    const int c4 = nv < 4 ? nv : 4;
    const float inv = 1.f / (float)(c4 + 1);
    for (int i = tid; i < H_; i += 128) {
        float s = 0.f;
        for (int t = 0; t < c4; t++)
            s += buf[((size_t)(b * 12 + ord[t])) * H_ + i];
        if (c4 == 4) s += zb[i];
        g_zl[(size_t)b * H_ + i]        = __float2half_rn(zb[i]);
        g_zl[(size_t)(B_ + b) * H_ + i] = __float2half_rn(s * inv);
    }
}

// ---------------------------------------------------------------------------
// fp16 tensor-core GEMM (128x128x32 tiles, 4-stage cp.async, ldmatrix+mma).
//   dynM != 0: CTAs whose M-tile starts beyond g_Mtot exit early.
//   bias2/bsplit: tiles starting at row >= bsplit use bias2 (stacked GEMM).
//   epi: 0 fp32, 1 fp32+resid, 2 relu->half, 3 tanh fp32, 4 half
// ---------------------------------------------------------------------------
#define NSTG 4
constexpr int A_STRIDE_B = 80;
constexpr int B_STRIDE_B = 272;
constexpr int A_BYTES = 128 * A_STRIDE_B;  // 10240
constexpr int B_BYTES = 32 * B_STRIDE_B;   // 8704
constexpr int STAGE   = A_BYTES + B_BYTES; // 18944

__global__ void __launch_bounds__(256, 2)
gemm_f16(const __half* __restrict__ A, const __half* __restrict__ W,
         const float* __restrict__ bias, const float* __restrict__ bias2, int bsplit,
         const float* __restrict__ resid,
         void* __restrict__ Cout, int N, int K, int epi, int dynM)
{
    const int bn = blockIdx.x, bm = blockIdx.y;
    if (dynM && bm * 128 >= g_Mtot) return;

    extern __shared__ __align__(16) char smc[];
    const int tid = threadIdx.x, wid = tid >> 5, lane = tid & 31;
    const int wm = (wid & 1) * 64;
    const int wn = (wid >> 1) * 32;

    const uint32_t sbase = (uint32_t)__cvta_generic_to_shared(smc);
    const __half* Ab = A + (size_t)(bm * 128) * K;
    const float* bp = (bias2 && bm * 128 >= bsplit) ? bias2 : bias;

    float acc[4][4][4];
#pragma unroll
    for (int mi = 0; mi < 4; mi++)
#pragma unroll
        for (int ni = 0; ni < 4; ni++)
#pragma unroll
            for (int r = 0; r < 4; r++) acc[mi][ni][r] = 0.f;

    auto load_stage = [&](int s, int kt) {
        uint32_t as = sbase + s * STAGE;
        uint32_t bs = as + A_BYTES;
        const __half* Ak = Ab + kt * 32;
        const __half* Wk = W + (size_t)(kt * 32) * N + bn * 128;
#pragma unroll
        for (int i = 0; i < 2; i++) {
            int idx = tid + (i << 8);
            int r = idx >> 2, c = idx & 3;
            cpasync16(as + r * A_STRIDE_B + c * 16, Ak + (size_t)r * K + c * 8);
        }
#pragma unroll
        for (int i = 0; i < 2; i++) {
            int idx = tid + (i << 8);
            int r = idx >> 4, c = idx & 15;
            cpasync16(bs + r * B_STRIDE_B + c * 16, Wk + (size_t)r * N + c * 8);
        }
        asm volatile("cp.async.commit_group;\n" ::: "memory");
    };

    const int NIT = K >> 5;
#pragma unroll
    for (int s = 0; s < NSTG - 1; s++) load_stage(s, s);

    const int l15 = lane & 15;
    const int l16 = (lane >> 4) << 3;

    for (int it = 0; it < NIT; it++) {
        asm volatile("cp.async.wait_group %0;\n" :: "n"(NSTG - 2) : "memory");
        __syncthreads();
        if (it + NSTG - 1 < NIT) load_stage((it + NSTG - 1) & (NSTG - 1), it + NSTG - 1);
        else asm volatile("cp.async.commit_group;\n" ::: "memory");

        const int s = it & (NSTG - 1);
        const uint32_t as = sbase + s * STAGE;
        const uint32_t bs = as + A_BYTES;
#pragma unroll
        for (int kh = 0; kh < 2; kh++) {
            const int kc = kh * 16;
            uint32_t a[4][4], b[2][4];
#pragma unroll
            for (int mi = 0; mi < 4; mi++)
                ldsm4(a[mi], as + (wm + mi * 16 + l15) * A_STRIDE_B + (kc + l16) * 2);
#pragma unroll
            for (int np = 0; np < 2; np++)
                ldsm4t(b[np], bs + (kc + l15) * B_STRIDE_B + (wn + np * 16 + l16) * 2);
#pragma unroll
            for (int mi = 0; mi < 4; mi++)
#pragma unroll
                for (int ni = 0; ni < 4; ni++)
                    mma16816(acc[mi][ni], a[mi],
                             b[ni >> 1][(ni & 1) * 2], b[ni >> 1][(ni & 1) * 2 + 1]);
        }
    }

    const int g = lane >> 2, tg = lane & 3;
    const int row0 = bm * 128 + wm;
    const int col0 = bn * 128 + wn;
#pragma unroll
    for (int mi = 0; mi < 4; mi++) {
#pragma unroll
        for (int ni = 0; ni < 4; ni++) {
            const int c = col0 + ni * 8 + tg * 2;
            float2 bv = *(const float2*)(bp + c);
#pragma unroll
            for (int hh = 0; hh < 2; hh++) {
                const int r = row0 + mi * 16 + g + hh * 8;
                float v0 = acc[mi][ni][hh * 2]     + bv.x;
                float v1 = acc[mi][ni][hh * 2 + 1] + bv.y;
                const size_t off = (size_t)r * N + c;
                if (epi == 1) {
                    float2 rv = *(const float2*)(resid + off);
                    v0 += rv.x; v1 += rv.y;
                    *(float2*)((float*)Cout + off) = make_float2(v0, v1);
                } else if (epi == 2) {
                    v0 = fmaxf(v0, 0.f); v1 = fmaxf(v1, 0.f);
                    *(__half2*)((__half*)Cout + off) = __floats2half2_rn(v0, v1);
                } else if (epi == 3) {
                    *(float2*)((float*)Cout + off) = make_float2(tanhf(v0), tanhf(v1));
                } else if (epi == 4) {
                    *(__half2*)((__half*)Cout + off) = __floats2half2_rn(v0, v1);
                } else {
                    *(float2*)((float*)Cout + off) = make_float2(v0, v1);
                }
            }
        }
    }
}

// ---------------------------------------------------------------------------
// Attention on compacted rows: one CTA per (batch, head), L = g_len[b] rows.
// QKV read as half, compute fp32.
// ---------------------------------------------------------------------------
__global__ void attn_kernel() {
    const int b = blockIdx.x, h = blockIdx.y;
    __shared__ float q[12][97], k[12][97], v[12][97];
    __shared__ float sc[12][12];
    const int tid = threadIdx.x; // 128
    const int L = g_len[b];
    const int off = g_off[b];
    const size_t qkvbase = (size_t)off * H3_ + h * 96;

    for (int i = tid; i < L * 96; i += 128) {
        int t = i / 96, d = i % 96;
        size_t o = qkvbase + (size_t)t * H3_ + d;
        q[t][d] = __half2float(g_QKVh[o]);
        k[t][d] = __half2float(g_QKVh[o + H_]);
        v[t][d] = __half2float(g_QKVh[o + 2 * H_]);
    }
    __syncthreads();

    for (int p = tid; p < L * L; p += 128) {
        int qi = p / L, ki = p % L;
        float s = 0.f;
#pragma unroll
        for (int d = 0; d < 96; d++) s += q[qi][d] * k[ki][d];
        sc[qi][ki] = s * 0.10206207261596577f;
    }
    __syncthreads();

    if (tid < L) {
        float m = -3.0e38f;
        for (int j = 0; j < L; j++) m = fmaxf(m, sc[tid][j]);
        float sum = 0.f;
        for (int j = 0; j < L; j++) { float e = expf(sc[tid][j] - m); sc[tid][j] = e; sum += e; }
        float r = 1.f / sum;
        for (int j = 0; j < L; j++) sc[tid][j] *= r;
    }
    __syncthreads();

    const size_t pbase = (size_t)off * H_ + h * 96;
    for (int i = tid; i < L * 96; i += 128) {
        int qi = i / 96, d = i % 96;
        float o = 0.f;
        for (int j = 0; j < L; j++) o += sc[qi][j] * v[j][d];
        g_Ph[pbase + (size_t)qi * H_ + d] = __float2half_rn(o);
    }
}

// ---------------------------------------------------------------------------
// Row LayerNorm over H=768 (one CTA per row). Early exit beyond g_Mtot.
// ---------------------------------------------------------------------------
__global__ void ln_kernel(const float* __restrict__ X,
                          const float* __restrict__ gam,
                          const float* __restrict__ bet,
                          float* __restrict__ Of, __half* __restrict__ Oh) {
    const int row = blockIdx.x;
    if (row >= g_Mtot) return;
    const int tid = threadIdx.x; // 256
    const float* x = X + (size_t)row * H_;
    float vals[3];
    float s = 0.f, s2 = 0.f;
#pragma unroll
    for (int i = 0; i < 3; i++) {
        float t = x[tid + i * 256];
        vals[i] = t; s += t; s2 += t * t;
    }
    __shared__ float red[2][8];
    s  = warp_red(s);
    s2 = warp_red(s2);
    if ((tid & 31) == 0) { red[0][tid >> 5] = s; red[1][tid >> 5] = s2; }
    __syncthreads();
    float ts = 0.f, ts2 = 0.f;
#pragma unroll
    for (int w = 0; w < 8; w++) { ts += red[0][w]; ts2 += red[1][w]; }
    const float mu  = ts * (1.f / 768.f);
    const float var = ts2 * (1.f / 768.f) - mu * mu;
    const float inv = rsqrtf(var + 1e-5f);
#pragma unroll
    for (int i = 0; i < 3; i++) {
        int c = tid + i * 256;
        float r = (vals[i] - mu) * inv * gam[c] + bet[c];
        Of[(size_t)row * H_ + c] = r;
        Oh[(size_t)row * H_ + c] = __float2half_rn(r);
    }
}

// ---------------------------------------------------------------------------
// Final: fused LN2 over the batch's live rows + mean pool + gate + mix.
// One CTA per batch element, 256 threads.
// ---------------------------------------------------------------------------
__global__ void final_kernel(const float* __restrict__ Y,
                             const float* __restrict__ ln2g,
                             const float* __restrict__ ln2b,
                             const float* __restrict__ Wg,
                             const float* __restrict__ bg,
                             float* __restrict__ out) {
    const int b = blockIdx.x, tid = threadIdx.x; // 256
    const int L = g_len[b];
    const int off = g_off[b];
    const float invL = 1.f / (float)L;

    float gm[3], bt[3];
#pragma unroll
    for (int i = 0; i < 3; i++) {
        int c = tid + i * 256;
        gm[i] = ln2g[c];
        bt[i] = ln2b[c];
    }

    __shared__ float red[2][8];
    float xgacc[3] = {0.f, 0.f, 0.f};
    for (int t = 0; t < L; t++) {
        const float* x = Y + (size_t)(off + t) * H_;
        float vals[3];
        float s = 0.f, s2 = 0.f;
#pragma unroll
        for (int i = 0; i < 3; i++) {
            float v = x[tid + i * 256];
            vals[i] = v; s += v; s2 += v * v;
        }
        s  = warp_red(s);
        s2 = warp_red(s2);
        if ((tid & 31) == 0) { red[0][tid >> 5] = s; red[1][tid >> 5] = s2; }
        __syncthreads();
        float ts = 0.f, ts2 = 0.f;
#pragma unroll
        for (int w = 0; w < 8; w++) { ts += red[0][w]; ts2 += red[1][w]; }
        const float mu  = ts * (1.f / 768.f);
        const float var = ts2 * (1.f / 768.f) - mu * mu;
        const float inv = rsqrtf(var + 1e-5f);
#pragma unroll
        for (int i = 0; i < 3; i++)
            xgacc[i] += (vals[i] - mu) * inv * gm[i] + bt[i];
        __syncthreads();
    }

    float xd[3], xl[3], xg[3];
    float p0 = 0.f, p1 = 0.f, p2 = 0.f;
#pragma unroll
    for (int i = 0; i < 3; i++) {
        int c = tid + i * 256;
        xd[i] = g_xdl[(size_t)b * H_ + c];
        xl[i] = g_xdl[(size_t)(B_ + b) * H_ + c];
        xg[i] = xgacc[i] * invL;
        p0 += xd[i] * Wg[c * 3 + 0] + xl[i] * Wg[(768 + c) * 3 + 0] + xg[i] * Wg[(1536 + c) * 3 + 0];
        p1 += xd[i] * Wg[c * 3 + 1] + xl[i] * Wg[(768 + c) * 3 + 1] + xg[i] * Wg[(1536 + c) * 3 + 1];
        p2 += xd[i] * Wg[c * 3 + 2] + xl[i] * Wg[(768 + c) * 3 + 2] + xg[i] * Wg[(1536 + c) * 3 + 2];
    }
    p0 = warp_red(p0); p1 = warp_red(p1); p2 = warp_red(p2);
    __shared__ float red3[8][3];
    if ((tid & 31) == 0) { red3[tid >> 5][0] = p0; red3[tid >> 5][1] = p1; red3[tid >> 5][2] = p2; }
    __syncthreads();
    float l0 = bg[0], l1 = bg[1], l2 = bg[2];
#pragma unroll
    for (int w = 0; w < 8; w++) { l0 += red3[w][0]; l1 += red3[w][1]; l2 += red3[w][2]; }
    float m  = fmaxf(l0, fmaxf(l1, l2));
    float e0 = expf(l0 - m), e1 = expf(l1 - m), e2 = expf(l2 - m);
    float rs = 1.f / (e0 + e1 + e2);
    float g0 = e0 * rs, g1 = e1 * rs, g2 = e2 * rs;
#pragma unroll
    for (int i = 0; i < 3; i++) {
        int c = tid + i * 256;
        out[(size_t)b * H_ + c] = g0 * xd[i] + g1 * xl[i] + g2 * xg[i];
    }
}

// ---------------------------------------------------------------------------
// Launch
// ---------------------------------------------------------------------------
extern "C" void kernel_launch(void* const* d_in, const int* in_sizes, int n_in,
                              void* d_out, int out_size) {
    const float* z_k  = (const float*)d_in[0];
    const float* ctx  = (const float*)d_in[1];
    const int*   mask = (const int*)  d_in[2];
    const int*   bidx = (const int*)  d_in[3];
    const float* Wq = (const float*)d_in[4];  const float* bq = (const float*)d_in[5];
    const float* Wk = (const float*)d_in[6];  const float* bk = (const float*)d_in[7];
    const float* Wv = (const float*)d_in[8];  const float* bv = (const float*)d_in[9];
    const float* Wo = (const float*)d_in[10]; const float* bo = (const float*)d_in[11];
    const float* ln1g = (const float*)d_in[12]; const float* ln1b = (const float*)d_in[13];
    const float* W1 = (const float*)d_in[14]; const float* b1 = (const float*)d_in[15];
    const float* W2 = (const float*)d_in[16]; const float* b2 = (const float*)d_in[17];
    const float* ln2g = (const float*)d_in[18]; const float* ln2b = (const float*)d_in[19];
    const float* Wd = (const float*)d_in[20]; const float* bd = (const float*)d_in[21];
    const float* Wl = (const float*)d_in[22]; const float* bl = (const float*)d_in[23];
    const float* Wg = (const float*)d_in[24]; const float* bg = (const float*)d_in[25];
    float* out = (float*)d_out;

    static bool attr_done = false;
    const int dynSmem = NSTG * STAGE;
    if (!attr_done) {
        cudaFuncSetAttribute(gemm_f16, cudaFuncAttributeMaxDynamicSharedMemorySize, dynSmem);
        attr_done = true;
    }

    void *pgf, *pgh, *pqkv, *pph, *py, *px1f, *px1h, *pffh;
    void *pzl, *pxdl, *pwh, *pbqkv;
    cudaGetSymbolAddress(&pgf,  g_gseqf);  cudaGetSymbolAddress(&pgh,  g_gseqh);
    cudaGetSymbolAddress(&pqkv, g_QKVh);   cudaGetSymbolAddress(&pph,  g_Ph);
    cudaGetSymbolAddress(&py,   g_Y);      cudaGetSymbolAddress(&px1f, g_X1f);
    cudaGetSymbolAddress(&px1h, g_X1h);    cudaGetSymbolAddress(&pffh, g_FFh);
    cudaGetSymbolAddress(&pzl,  g_zl);     cudaGetSymbolAddress(&pxdl, g_xdl);
    cudaGetSymbolAddress(&pwh,  g_Wh);     cudaGetSymbolAddress(&pbqkv, g_bqkv);

    float*  fgf  = (float*)pgf;    __half* fgh  = (__half*)pgh;
    __half* fqkv = (__half*)pqkv;  __half* fph  = (__half*)pph;
    float*  fy   = (float*)py;     float*  fx1f = (float*)px1f;
    __half* fx1h = (__half*)px1h;  __half* fffh = (__half*)pffh;
    __half* fzl  = (__half*)pzl;   float*  fxdl = (float*)pxdl;
    __half* fwh  = (__half*)pwh;   float*  fbqkv = (float*)pbqkv;

    // Weight / bias prep (fp16, [K][N] row-major, QKV fused)
    const int nHH = H_ * H_;
    pack_qkv<<<(nHH + 255) / 256, 256>>>(Wq, Wk, Wv, fwh + OFF_QKV);
    convh<<<(nHH + 255) / 256, 256>>>(Wo, fwh + OFF_WO, nHH);
    convh<<<(H_ * FF_ + 255) / 256, 256>>>(W1, fwh + OFF_W1, H_ * FF_);
    convh<<<(FF_ * H_ + 255) / 256, 256>>>(W2, fwh + OFF_W2, FF_ * H_);
    convh<<<(nHH + 255) / 256, 256>>>(Wd, fwh + OFF_WD, nHH);
    convh<<<(nHH + 255) / 256, 256>>>(Wl, fwh + OFF_WL, nHH);
    pack_bias<<<(H_ + 255) / 256, 256>>>(bq, bk, bv, fbqkv);

    // Compaction bookkeeping + gather
    len_kernel<<<(B_ + 255) / 256, 256>>>(mask);
    scan_kernel<<<1, 1024>>>();
    gather_kernel<<<B_, 128>>>(z_k, ctx, mask, bidx);

    // Stacked direct+local paths: [z; lpool] (2B x 768) @ [Wd|Wl] with tanh.
    // Uses WD for rows [0,B), WL for rows [B,2B) via two N-identical GEMMs on
    // the two row halves (same kernel, bias split).
    gemm_f16<<<dim3(H_ / 128, B_ / 128), 256, dynSmem>>>(
        fzl, fwh + OFF_WD, bd, nullptr, 0, nullptr, fxdl, H_, H_, 3, 0);
    gemm_f16<<<dim3(H_ / 128, B_ / 128), 256, dynSmem>>>(
        fzl + (size_t)B_ * H_, fwh + OFF_WL, bl, nullptr, 0, nullptr,
        fxdl + (size_t)B_ * H_, H_, H_, 3, 0);

    // Fused QKV projection (N = 2304), compacted rows, half output
    gemm_f16<<<dim3(H3_ / 128, MR_ / 128), 256, dynSmem>>>(
        fgh, fwh + OFF_QKV, fbqkv, nullptr, 0, nullptr, fqkv, H3_, H_, 4, 1);
    // Attention
    attn_kernel<<<dim3(B_, 8), 128>>>();
    // Output projection + residual (gseq fp32), LN1
    gemm_f16<<<dim3(H_ / 128, MR_ / 128), 256, dynSmem>>>(
        fph, fwh + OFF_WO, bo, nullptr, 0, fgf, fy, H_, H_, 1, 1);
    ln_kernel<<<MR_, 256>>>(fy, ln1g, ln1b, fx1f, fx1h);
    // FFN
    gemm_f16<<<dim3(FF_ / 128, MR_ / 128), 256, dynSmem>>>(
        fx1h, fwh + OFF_W1, b1, nullptr, 0, nullptr, fffh, FF_, H_, 2, 1);
    gemm_f16<<<dim3(H_ / 128, MR_ / 128), 256, dynSmem>>>(
        fffh, fwh + OFF_W2, b2, nullptr, 0, fx1f, fy, H_, FF_, 1, 1);
    // Fused LN2 + pool + gate + output
    final_kernel<<<B_, 256>>>(fy, ln2g, ln2b, Wg, bg, out);
}